// round 10
// baseline (speedup 1.0000x reference)
#include <cuda_runtime.h>

#define BATCH 4
#define NQ    2048
#define NK    2048
#define DQ    1024
#define NH    8
#define HD    64
#define INNER 512
#define KKEEP 64
#define CH    64          // key chunk width in fused kernel
#define NCH   (NK / CH)   // 32
#define SCW   66          // score tile stride (EVEN -> float2 stores stay 8B-aligned)

// Scratch (device globals; allocation-free contract)
__device__ float g_Q [BATCH * NQ * INNER];          // 16.8 MB
__device__ float g_KV[BATCH * NK * 2 * INNER];      // 33.5 MB  (K: cols 0..511, V: 512..1023)
__device__ float g_O [BATCH * NQ * INNER];          // 16.8 MB

// ---- tf32 split helpers + warp MMA --------------------------------------------
__device__ __forceinline__ void split_tf32(float v, unsigned& hi, unsigned& lo) {
    asm("cvt.rna.tf32.f32 %0, %1;" : "=r"(hi) : "f"(v));
    float l = v - __uint_as_float(hi);
    asm("cvt.rna.tf32.f32 %0, %1;" : "=r"(lo) : "f"(l));
}

#define MMA_TF32(c, a, b0, b1) \
    asm("mma.sync.aligned.m16n8k8.row.col.f32.tf32.tf32.f32 " \
        "{%0,%1,%2,%3}, {%4,%5,%6,%7}, {%8,%9}, {%0,%1,%2,%3};" \
        : "+f"((c)[0]), "+f"((c)[1]), "+f"((c)[2]), "+f"((c)[3]) \
        : "r"((a)[0]), "r"((a)[1]), "r"((a)[2]), "r"((a)[3]), "r"(b0), "r"(b1))

__device__ __forceinline__ unsigned fkey(float f) {
    unsigned u = __float_as_uint(f);
    return (u & 0x80000000u) ? ~u : (u | 0x80000000u);
}
__device__ __forceinline__ float unfkey(unsigned k) {
    unsigned u = (k & 0x80000000u) ? (k & 0x7fffffffu) : ~k;
    return __uint_as_float(u);
}

// ---------------------------------------------------------------------------
// fp32 SGEMM (NN), double-buffered, ld-parameterized (Q and K projections).
// ---------------------------------------------------------------------------
__global__ void __launch_bounds__(256) sgemm_nn(
    const float* __restrict__ A, const float* __restrict__ Bm,
    float* __restrict__ C, int M, int N, int K, int lda, int ldb, int ldc)
{
    __shared__ float As[2][8][128];
    __shared__ float Bs[2][8][128];
    const int tid  = threadIdx.x;
    const int row0 = blockIdx.y * 128, col0 = blockIdx.x * 128;
    const int tx   = tid & 15, ty = tid >> 4;
    const int a_row = tid >> 1, a_k = (tid & 1) * 4;
    const int b_k   = tid >> 5, b_col = (tid & 31) * 4;
    const float* Ap = A  + (size_t)(row0 + a_row) * lda + a_k;
    const float* Bp = Bm + (size_t)b_k * ldb + col0 + b_col;

    float acc[8][8];
#pragma unroll
    for (int i = 0; i < 8; i++)
#pragma unroll
        for (int j = 0; j < 8; j++) acc[i][j] = 0.f;

    {
        float4 av = *(const float4*)Ap;
        float4 bv = *(const float4*)Bp;
        As[0][a_k + 0][a_row] = av.x;
        As[0][a_k + 1][a_row] = av.y;
        As[0][a_k + 2][a_row] = av.z;
        As[0][a_k + 3][a_row] = av.w;
        *(float4*)&Bs[0][b_k][b_col] = bv;
    }
    __syncthreads();

    int buf = 0;
    for (int k0 = 8; k0 <= K; k0 += 8) {
        const bool has = (k0 < K);
        float4 av, bv;
        if (has) {
            av = *(const float4*)(Ap + k0);
            bv = *(const float4*)(Bp + (size_t)k0 * ldb);
        }
#pragma unroll
        for (int kk = 0; kk < 8; kk++) {
            float af[8], bf[8];
            *(float4*)&af[0] = *(const float4*)&As[buf][kk][ty * 4];
            *(float4*)&af[4] = *(const float4*)&As[buf][kk][ty * 4 + 64];
            *(float4*)&bf[0] = *(const float4*)&Bs[buf][kk][tx * 4];
            *(float4*)&bf[4] = *(const float4*)&Bs[buf][kk][tx * 4 + 64];
#pragma unroll
            for (int i = 0; i < 8; i++)
#pragma unroll
                for (int j = 0; j < 8; j++)
                    acc[i][j] += af[i] * bf[j];
        }
        if (has) {
            const int nb = buf ^ 1;
            As[nb][a_k + 0][a_row] = av.x;
            As[nb][a_k + 1][a_row] = av.y;
            As[nb][a_k + 2][a_row] = av.z;
            As[nb][a_k + 3][a_row] = av.w;
            *(float4*)&Bs[nb][b_k][b_col] = bv;
            __syncthreads();
            buf = nb;
        }
    }

#pragma unroll
    for (int ih = 0; ih < 2; ih++)
#pragma unroll
        for (int ii = 0; ii < 4; ii++) {
            int row = row0 + ty * 4 + ih * 64 + ii;
            float* Cp = C + (size_t)row * ldc + col0;
#pragma unroll
            for (int jh = 0; jh < 2; jh++) {
                int c = tx * 4 + jh * 64;
                float4 v;
                v.x = acc[ih * 4 + ii][jh * 4 + 0];
                v.y = acc[ih * 4 + ii][jh * 4 + 1];
                v.z = acc[ih * 4 + ii][jh * 4 + 2];
                v.w = acc[ih * 4 + ii][jh * 4 + 3];
                *(float4*)(Cp + c) = v;
            }
        }
}

// ---------------------------------------------------------------------------
// Generic 3xTF32 MMA GEMM (NN): C = A @ B (+ bias), ld-parameterized.
// Used for V-half projection and out-projection (both post-selection safe).
// ---------------------------------------------------------------------------
__global__ void __launch_bounds__(256) gemm_tf32_nn(
    const float* __restrict__ A, const float* __restrict__ Bm,
    const float* __restrict__ bias, float* __restrict__ C,
    int M, int N, int K, int lda, int ldb, int ldc)
{
    __shared__ float As[2][128 * 12];
    __shared__ float Bs[2][128 * 12];
    const int tid  = threadIdx.x;
    const int row0 = blockIdx.y * 128, col0 = blockIdx.x * 128;
    const int a_row = tid >> 1, a_k = (tid & 1) * 4;
    const int b_k   = tid >> 5, b_n = (tid & 31) * 4;
    const float* Ap = A  + (size_t)(row0 + a_row) * lda + a_k;
    const float* Bp = Bm + (size_t)b_k * ldb + col0 + b_n;

    {
        float4 a4 = *(const float4*)Ap;
        *(float4*)(As[0] + a_row * 12 + a_k) = a4;
        float4 b4 = *(const float4*)Bp;
        Bs[0][(b_n + 0) * 12 + b_k] = b4.x;
        Bs[0][(b_n + 1) * 12 + b_k] = b4.y;
        Bs[0][(b_n + 2) * 12 + b_k] = b4.z;
        Bs[0][(b_n + 3) * 12 + b_k] = b4.w;
    }
    __syncthreads();

    const int lane = tid & 31, wid = tid >> 5;
    const int wm = (wid & 3) * 32, wn = (wid >> 2) * 64;
    const int gr = lane >> 2, gc = lane & 3;

    float acc[2][8][4];
#pragma unroll
    for (int mi = 0; mi < 2; mi++)
#pragma unroll
        for (int ni = 0; ni < 8; ni++)
#pragma unroll
            for (int q = 0; q < 4; q++) acc[mi][ni][q] = 0.f;

    int buf = 0;
    for (int k0 = 8; k0 <= K; k0 += 8) {
        const bool has = (k0 < K);
        float4 a4, b4;
        if (has) {
            a4 = *(const float4*)(Ap + k0);
            b4 = *(const float4*)(Bp + (size_t)k0 * ldb);
        }
        unsigned ahi[2][4], alo[2][4];
#pragma unroll
        for (int mi = 0; mi < 2; mi++) {
            int m = wm + mi * 16 + gr;
            split_tf32(As[buf][m * 12 + gc],           ahi[mi][0], alo[mi][0]);
            split_tf32(As[buf][(m + 8) * 12 + gc],     ahi[mi][1], alo[mi][1]);
            split_tf32(As[buf][m * 12 + 4 + gc],       ahi[mi][2], alo[mi][2]);
            split_tf32(As[buf][(m + 8) * 12 + 4 + gc], ahi[mi][3], alo[mi][3]);
        }
#pragma unroll
        for (int ni = 0; ni < 8; ni++) {
            int n = wn + ni * 8 + gr;
            unsigned bh0, bl0, bh1, bl1;
            split_tf32(Bs[buf][n * 12 + gc],     bh0, bl0);
            split_tf32(Bs[buf][n * 12 + 4 + gc], bh1, bl1);
#pragma unroll
            for (int mi = 0; mi < 2; mi++) {
                MMA_TF32(acc[mi][ni], ahi[mi], bh0, bh1);
                MMA_TF32(acc[mi][ni], ahi[mi], bl0, bl1);
                MMA_TF32(acc[mi][ni], alo[mi], bh0, bh1);
            }
        }
        if (has) {
            const int nb = buf ^ 1;
            *(float4*)(As[nb] + a_row * 12 + a_k) = a4;
            Bs[nb][(b_n + 0) * 12 + b_k] = b4.x;
            Bs[nb][(b_n + 1) * 12 + b_k] = b4.y;
            Bs[nb][(b_n + 2) * 12 + b_k] = b4.z;
            Bs[nb][(b_n + 3) * 12 + b_k] = b4.w;
            __syncthreads();
            buf = nb;
        }
    }

#pragma unroll
    for (int mi = 0; mi < 2; mi++)
#pragma unroll
        for (int ni = 0; ni < 8; ni++) {
            int row = row0 + wm + mi * 16 + gr;
            int col = col0 + wn + ni * 8 + gc * 2;
            float bx = 0.f, by = 0.f;
            if (bias) { bx = bias[col]; by = bias[col + 1]; }
            float2 v0 = { acc[mi][ni][0] + bx, acc[mi][ni][1] + by };
            *(float2*)(C + (size_t)row * ldc + col) = v0;
            float2 v1 = { acc[mi][ni][2] + bx, acc[mi][ni][3] + by };
            *(float2*)(C + (size_t)(row + 8) * ldc + col) = v1;
        }
}

// ---------------------------------------------------------------------------
// FUSED sim + exact top-64 + softmax + PV.  One block = 128 query rows of one
// (b,h).  Warps 4-7: 3-term TF32 MMA producing 128x64 score chunks into
// double-buffered smem (bitwise-identical S values to the standalone sim).
// Warps 0-3 (1 thread/row): stream the previous chunk into a 64-entry min-heap
// of composite keys (fkey(v)<<32)|(2047-j)  == jax.lax.top_k order incl. ties.
// Tail: per-row softmax from heap + cooperative PV gather + O write.
// ---------------------------------------------------------------------------
__global__ void __launch_bounds__(256) simtopk(
    const float* __restrict__ Q, const float* __restrict__ KV, float* __restrict__ O)
{
    extern __shared__ char smraw[];
    float* Qs = (float*)smraw;                       // [128][68]
    float* Ks = Qs + 128 * 68;                       // 2 x [64][68]
    float* Sc = Ks + 2 * 64 * 68;                    // 2 x [128][SCW]  (SCW even!)
    unsigned long long* Hp =
        (unsigned long long*)(Sc + 2 * 128 * SCW);   // [128][65] u64 (stride 65)
    __shared__ float wsumArr[128];

    const int bh = blockIdx.y, b = bh >> 3, h = bh & 7;
    const int i0 = blockIdx.x * 128;
    const int tid = threadIdx.x;
    const int lane = tid & 31, wid = tid >> 5;

    // ---- prologue: Q tile, K chunk 0, heap init -------------------------------
#pragma unroll
    for (int l = 0; l < 8; l++) {
        int idx = tid + l * 256;                 // 0..2047
        int row = idx >> 4, d4 = (idx & 15) * 4;
        float4 q4 = *(const float4*)(Q + (size_t)(b * NQ + i0 + row) * INNER + h * HD + d4);
        *(float4*)(Qs + row * 68 + d4) = q4;
    }
#pragma unroll
    for (int l = 0; l < 4; l++) {
        int idx = tid + l * 256;                 // 0..1023
        int row = idx >> 4, d4 = (idx & 15) * 4;
        float4 k4 = *(const float4*)(KV + (size_t)(b * NK + row) * (2 * INNER) + h * HD + d4);
        *(float4*)(Ks + row * 68 + d4) = k4;
    }
#pragma unroll
    for (int l = 0; l < 32; l++) {
        int idx = tid + l * 256;                 // 0..8191 -> covers all r<128,e<64
        int r = idx >> 6, e = idx & 63;
        Hp[r * 65 + e] = 0ull;
    }
    __syncthreads();

    const int gr = lane >> 2, gc = lane & 3;
    const int wid4 = wid - 4;                    // mma warp id 0..3
    const int wm = wid4 * 32;

    // ---- main loop: chunk c produced by mma warps, chunk c-1 consumed ---------
    for (int c = 0; c <= NCH; c++) {
        __syncthreads();
        if (wid >= 4) {
            if (c < NCH) {
                const int buf = c & 1;
                // prefetch K chunk c+1 into regs
                float4 kpre[8];
                const bool pre = (c + 1 < NCH);
                if (pre) {
                    int jb2 = (c + 1) * CH;
                    int t2 = tid - 128;
#pragma unroll
                    for (int l = 0; l < 8; l++) {
                        int idx = t2 + l * 128;
                        int row = idx >> 4, d4 = (idx & 15) * 4;
                        kpre[l] = *(const float4*)(KV +
                            (size_t)(b * NK + jb2 + row) * (2 * INNER) + h * HD + d4);
                    }
                }
                // mma 128x64 chunk (identical term order to standalone sim)
                float acc[2][8][4];
#pragma unroll
                for (int mi = 0; mi < 2; mi++)
#pragma unroll
                    for (int ni = 0; ni < 8; ni++)
#pragma unroll
                        for (int q = 0; q < 4; q++) acc[mi][ni][q] = 0.f;

                const float* Kb = Ks + buf * (64 * 68);
#pragma unroll
                for (int k0 = 0; k0 < 64; k0 += 8) {
                    unsigned ahi[2][4], alo[2][4];
#pragma unroll
                    for (int mi = 0; mi < 2; mi++) {
                        int m = wm + mi * 16 + gr;
                        split_tf32(Qs[m * 68 + k0 + gc],           ahi[mi][0], alo[mi][0]);
                        split_tf32(Qs[(m + 8) * 68 + k0 + gc],     ahi[mi][1], alo[mi][1]);
                        split_tf32(Qs[m * 68 + k0 + 4 + gc],       ahi[mi][2], alo[mi][2]);
                        split_tf32(Qs[(m + 8) * 68 + k0 + 4 + gc], ahi[mi][3], alo[mi][3]);
                    }
#pragma unroll
                    for (int ni = 0; ni < 8; ni++) {
                        int n = ni * 8 + gr;
                        unsigned bh0, bl0, bh1, bl1;
                        split_tf32(Kb[n * 68 + k0 + gc],     bh0, bl0);
                        split_tf32(Kb[n * 68 + k0 + 4 + gc], bh1, bl1);
#pragma unroll
                        for (int mi = 0; mi < 2; mi++) {
                            MMA_TF32(acc[mi][ni], ahi[mi], bh0, bh1);
                            MMA_TF32(acc[mi][ni], ahi[mi], bl0, bl1);
                            MMA_TF32(acc[mi][ni], alo[mi], bh0, bh1);
                        }
                    }
                }
                // scaled scores -> Sc[buf]  (SCW even => float2 stays aligned)
                const float scale = 0.125f;
                float* Sb = Sc + buf * (128 * SCW);
#pragma unroll
                for (int mi = 0; mi < 2; mi++)
#pragma unroll
                    for (int ni = 0; ni < 8; ni++) {
                        int row = wm + mi * 16 + gr;
                        int col = ni * 8 + gc * 2;
                        float2 v0 = { acc[mi][ni][0] * scale, acc[mi][ni][1] * scale };
                        *(float2*)(Sb + row * SCW + col) = v0;
                        float2 v1 = { acc[mi][ni][2] * scale, acc[mi][ni][3] * scale };
                        *(float2*)(Sb + (row + 8) * SCW + col) = v1;
                    }
                // store prefetched K chunk
                if (pre) {
                    float* Kn = Ks + ((c + 1) & 1) * (64 * 68);
                    int t2 = tid - 128;
#pragma unroll
                    for (int l = 0; l < 8; l++) {
                        int idx = t2 + l * 128;
                        int row = idx >> 4, d4 = (idx & 15) * 4;
                        *(float4*)(Kn + row * 68 + d4) = kpre[l];
                    }
                }
            }
        } else {
            if (c >= 1) {
                const int r = tid;               // 0..127
                const float* Srow = Sc + ((c - 1) & 1) * (128 * SCW) + r * SCW;
                const int jb = (c - 1) * CH;
                unsigned long long* H = Hp + r * 65;
                unsigned long long root = H[0];
                for (int jj = 0; jj < CH; jj++) {
                    float v = Srow[jj];
                    unsigned long long key =
                        ((unsigned long long)fkey(v) << 32) | (unsigned)(2047 - (jb + jj));
                    if (key > root) {
                        int p = 0;
                        while (true) {
                            int cl = 2 * p + 1;
                            if (cl >= 64) break;
                            unsigned long long hc = H[cl];
                            int cr = cl + 1;
                            if (cr < 64) {
                                unsigned long long h2 = H[cr];
                                if (h2 < hc) { hc = h2; cl = cr; }
                            }
                            if (hc >= key) break;
                            H[p] = hc; p = cl;
                        }
                        H[p] = key;
                        root = H[0];
                    }
                }
            }
        }
    }
    __syncthreads();

    // ---- weights: per-row max, exp, sum (reuse Sc space for w / idx) ----------
    float* wArr = Sc;                          // [r*SCW + k]
    int*   iArr = (int*)(Sc + 128 * SCW);      // [r*SCW + k]
    if (tid < 128) {
        const int r = tid;
        unsigned long long* H = Hp + r * 65;
        unsigned mh = 0;
#pragma unroll 8
        for (int k = 0; k < 64; k++) {
            unsigned hk = (unsigned)(H[k] >> 32);
            mh = (hk > mh) ? hk : mh;
        }
        float vmax = unfkey(mh);
        float ws = 0.f;
        for (int k = 0; k < 64; k++) {
            unsigned long long key = H[k];
            float v = unfkey((unsigned)(key >> 32));
            float wv = expf(v - vmax);
            ws += wv;
            wArr[r * SCW + k] = wv;
            iArr[r * SCW + k] = 2047 - (int)(unsigned)(key & 0xffffffffu);
        }
        wsumArr[r] = ws;
    }
    __syncthreads();

    // ---- PV: 2 threads/row x 32 dims; V gathered from L2 ----------------------
    {
        const int r = tid & 127, half = tid >> 7;
        const int d0 = half * 32;
        const float* Vb = KV + (size_t)b * NK * (2 * INNER) + INNER + h * HD + d0;
        float acc[32];
#pragma unroll
        for (int q = 0; q < 32; q++) acc[q] = 0.f;
        for (int k = 0; k < 64; k++) {
            float wk = wArr[r * SCW + k];
            int j = iArr[r * SCW + k];
            const float4* vp = (const float4*)(Vb + (size_t)j * (2 * INNER));
#pragma unroll
            for (int q = 0; q < 8; q++) {
                float4 v4 = vp[q];
                acc[q * 4 + 0] += wk * v4.x;
                acc[q * 4 + 1] += wk * v4.y;
                acc[q * 4 + 2] += wk * v4.z;
                acc[q * 4 + 3] += wk * v4.w;
            }
        }
        const float ws = wsumArr[r];
        float* Op = O + (size_t)(b * NQ + i0 + r) * INNER + h * HD + d0;
#pragma unroll
        for (int q = 0; q < 8; q++) {
            float4 v4;
            v4.x = acc[q * 4 + 0] / ws;
            v4.y = acc[q * 4 + 1] / ws;
            v4.z = acc[q * 4 + 2] / ws;
            v4.w = acc[q * 4 + 3] / ws;
            *(float4*)(Op + q * 4) = v4;
        }
    }
}

// ---------------------------------------------------------------------------
extern "C" void kernel_launch(void* const* d_in, const int* in_sizes, int n_in,
                              void* d_out, int out_size)
{
    const float* x    = (const float*)d_in[0];
    const float* ctx  = (const float*)d_in[1];
    const float* Wq   = (const float*)d_in[2];
    const float* Wkv  = (const float*)d_in[3];
    const float* Wout = (const float*)d_in[4];
    const float* bout = (const float*)d_in[5];
    float* out = (float*)d_out;

    float *pQ, *pKV, *pO;
    cudaGetSymbolAddress((void**)&pQ,  g_Q);
    cudaGetSymbolAddress((void**)&pKV, g_KV);
    cudaGetSymbolAddress((void**)&pO,  g_O);

    // fused smem: Q 128*68 + K 2*64*68 + Sc 2*128*SCW (fp32) + heap 128*65 (u64)
    const int fusedSmem = (128 * 68 + 2 * 64 * 68 + 2 * 128 * SCW) * 4 + 128 * 65 * 8;
    cudaFuncSetAttribute(simtopk, cudaFuncAttributeMaxDynamicSharedMemorySize, fusedSmem);

    dim3 blk(256);
    // Q = x @ Wq   (fp32; feeds selection)
    sgemm_nn<<<dim3(INNER / 128, BATCH * NQ / 128), blk>>>(
        x, Wq, pQ, BATCH * NQ, INNER, DQ, DQ, INNER, INNER);
    // K-half: ctx @ Wkv[:, 0:512]  (fp32; feeds selection)
    sgemm_nn<<<dim3(INNER / 128, BATCH * NK / 128), blk>>>(
        ctx, Wkv, pKV, BATCH * NK, INNER, DQ, DQ, 2 * INNER, 2 * INNER);
    // V-half: ctx @ Wkv[:, 512:1024]  (3xTF32; post-selection, safe)
    gemm_tf32_nn<<<dim3(INNER / 128, BATCH * NK / 128), blk>>>(
        ctx, Wkv + INNER, nullptr, pKV + INNER,
        BATCH * NK, INNER, DQ, DQ, 2 * INNER, 2 * INNER);
    // FUSED: sim (3-term TF32) + exact top-64 + softmax + PV
    simtopk<<<dim3(NQ / 128, BATCH * NH), blk, fusedSmem>>>(pQ, pKV, pO);
    // out = O @ Wout + bout (3xTF32)
    gemm_tf32_nn<<<dim3(DQ / 128, BATCH * NQ / 128), blk>>>(
        pO, Wout, bout, out, BATCH * NQ, DQ, INNER, INNER, DQ, DQ);
}

// round 11
// speedup vs baseline: 2.6234x; 2.6234x over previous
#include <cuda_runtime.h>

#define BATCH 4
#define NQ    2048
#define NK    2048
#define DQ    1024
#define NH    8
#define HD    64
#define INNER 512
#define KKEEP 64

// Scratch (device globals; allocation-free contract)
__device__ uint2 g_Qp[BATCH * NQ * INNER];          // 33.6 MB  packed (tf32 hi, lo)
__device__ uint2 g_Kp[BATCH * NK * INNER];          // 33.6 MB  packed (tf32 hi, lo)
__device__ float g_V [BATCH * NK * INNER];          // 16.8 MB
__device__ float g_S [134217728];                   // 512 MB   sim [B*H][NQ][NK]
__device__ float g_O [BATCH * NQ * INNER];          // 16.8 MB

// ---- tf32 split helpers + warp MMA --------------------------------------------
__device__ __forceinline__ void split_tf32(float v, unsigned& hi, unsigned& lo) {
    asm("cvt.rna.tf32.f32 %0, %1;" : "=r"(hi) : "f"(v));
    float l = v - __uint_as_float(hi);
    asm("cvt.rna.tf32.f32 %0, %1;" : "=r"(lo) : "f"(l));
}

#define MMA_TF32(c, a, b0, b1) \
    asm("mma.sync.aligned.m16n8k8.row.col.f32.tf32.tf32.f32 " \
        "{%0,%1,%2,%3}, {%4,%5,%6,%7}, {%8,%9}, {%0,%1,%2,%3};" \
        : "+f"((c)[0]), "+f"((c)[1]), "+f"((c)[2]), "+f"((c)[3]) \
        : "r"((a)[0]), "r"((a)[1]), "r"((a)[2]), "r"((a)[3]), "r"(b0), "r"(b1))

__device__ __forceinline__ unsigned fkey(float f) {
    unsigned u = __float_as_uint(f);
    return (u & 0x80000000u) ? ~u : (u | 0x80000000u);
}
__device__ __forceinline__ float unfkey(unsigned k) {
    unsigned u = (k & 0x80000000u) ? (k & 0x7fffffffu) : ~k;
    return __uint_as_float(u);
}

// ---------------------------------------------------------------------------
// fp32 SGEMM (NN), double-buffered; epilogue writes PACKED tf32 (hi,lo) pairs.
// Used for Q and K projections (fp32 accumulation preserves selection precision;
// the split is bitwise-identical to splitting the stored f32 later).
// ---------------------------------------------------------------------------
__global__ void __launch_bounds__(256) sgemm_nn_sp(
    const float* __restrict__ A, const float* __restrict__ Bm,
    uint2* __restrict__ C, int M, int N, int K, int lda, int ldb, int ldc)
{
    __shared__ float As[2][8][128];
    __shared__ float Bs[2][8][128];
    const int tid  = threadIdx.x;
    const int row0 = blockIdx.y * 128, col0 = blockIdx.x * 128;
    const int tx   = tid & 15, ty = tid >> 4;
    const int a_row = tid >> 1, a_k = (tid & 1) * 4;
    const int b_k   = tid >> 5, b_col = (tid & 31) * 4;
    const float* Ap = A  + (size_t)(row0 + a_row) * lda + a_k;
    const float* Bp = Bm + (size_t)b_k * ldb + col0 + b_col;

    float acc[8][8];
#pragma unroll
    for (int i = 0; i < 8; i++)
#pragma unroll
        for (int j = 0; j < 8; j++) acc[i][j] = 0.f;

    {
        float4 av = *(const float4*)Ap;
        float4 bv = *(const float4*)Bp;
        As[0][a_k + 0][a_row] = av.x;
        As[0][a_k + 1][a_row] = av.y;
        As[0][a_k + 2][a_row] = av.z;
        As[0][a_k + 3][a_row] = av.w;
        *(float4*)&Bs[0][b_k][b_col] = bv;
    }
    __syncthreads();

    int buf = 0;
    for (int k0 = 8; k0 <= K; k0 += 8) {
        const bool has = (k0 < K);
        float4 av, bv;
        if (has) {
            av = *(const float4*)(Ap + k0);
            bv = *(const float4*)(Bp + (size_t)k0 * ldb);
        }
#pragma unroll
        for (int kk = 0; kk < 8; kk++) {
            float af[8], bf[8];
            *(float4*)&af[0] = *(const float4*)&As[buf][kk][ty * 4];
            *(float4*)&af[4] = *(const float4*)&As[buf][kk][ty * 4 + 64];
            *(float4*)&bf[0] = *(const float4*)&Bs[buf][kk][tx * 4];
            *(float4*)&bf[4] = *(const float4*)&Bs[buf][kk][tx * 4 + 64];
#pragma unroll
            for (int i = 0; i < 8; i++)
#pragma unroll
                for (int j = 0; j < 8; j++)
                    acc[i][j] += af[i] * bf[j];
        }
        if (has) {
            const int nb = buf ^ 1;
            As[nb][a_k + 0][a_row] = av.x;
            As[nb][a_k + 1][a_row] = av.y;
            As[nb][a_k + 2][a_row] = av.z;
            As[nb][a_k + 3][a_row] = av.w;
            *(float4*)&Bs[nb][b_k][b_col] = bv;
            __syncthreads();
            buf = nb;
        }
    }

#pragma unroll
    for (int ih = 0; ih < 2; ih++)
#pragma unroll
        for (int ii = 0; ii < 4; ii++) {
            int row = row0 + ty * 4 + ih * 64 + ii;
            uint2* Cp = C + (size_t)row * ldc + col0;
#pragma unroll
            for (int jh = 0; jh < 2; jh++) {
                int c = tx * 4 + jh * 64;
                unsigned h0, l0, h1, l1, h2, l2, h3, l3;
                split_tf32(acc[ih * 4 + ii][jh * 4 + 0], h0, l0);
                split_tf32(acc[ih * 4 + ii][jh * 4 + 1], h1, l1);
                split_tf32(acc[ih * 4 + ii][jh * 4 + 2], h2, l2);
                split_tf32(acc[ih * 4 + ii][jh * 4 + 3], h3, l3);
                *(uint4*)(Cp + c)     = make_uint4(h0, l0, h1, l1);
                *(uint4*)(Cp + c + 2) = make_uint4(h2, l2, h3, l3);
            }
        }
}

// ---------------------------------------------------------------------------
// sim via 3-term TF32 MMA (NT) on PRE-SPLIT packed operands.
// No cvt in the inner loop: single LDS.64 per fragment element.
// Smem tiles stride 70 u64 (16B-aligned rows, conflict-free). 1 block/SM.
// Accumulation order identical to R8 -> bitwise-identical S.
// ---------------------------------------------------------------------------
__global__ void __launch_bounds__(256) sim_tf32p(
    const uint2* __restrict__ Qp, const uint2* __restrict__ Kp, float* __restrict__ S)
{
    extern __shared__ uint2 sm2[];
    uint2* Qs = sm2;               // [128][70]
    uint2* Ks = sm2 + 128 * 70;    // [128][70]
    const int bh = blockIdx.z, b = bh >> 3, h = bh & 7;
    const int i0 = blockIdx.y * 128, j0 = blockIdx.x * 128;
    const int tid = threadIdx.x;

#pragma unroll
    for (int l = 0; l < 16; l++) {
        int idx = tid + l * 256;                 // 0..4095
        int row = idx >> 5, c2 = (idx & 31) * 2; // 32 uint2-pairs per row
        uint4 q = *(const uint4*)(Qp + ((size_t)(b * NQ + i0 + row) * INNER + h * HD + c2));
        *(uint4*)(Qs + row * 70 + c2) = q;       // row*70+c2 even -> 16B aligned
        uint4 k = *(const uint4*)(Kp + ((size_t)(b * NK + j0 + row) * INNER + h * HD + c2));
        *(uint4*)(Ks + row * 70 + c2) = k;
    }
    __syncthreads();

    const int lane = tid & 31, wid = tid >> 5;
    const int wm = (wid & 3) * 32, wn = (wid >> 2) * 64;
    const int gr = lane >> 2, gc = lane & 3;

    float acc[2][8][4];
#pragma unroll
    for (int mi = 0; mi < 2; mi++)
#pragma unroll
        for (int ni = 0; ni < 8; ni++)
#pragma unroll
            for (int q = 0; q < 4; q++) acc[mi][ni][q] = 0.f;

#pragma unroll
    for (int k0 = 0; k0 < 64; k0 += 8) {
        unsigned ahi[2][4], alo[2][4];
#pragma unroll
        for (int mi = 0; mi < 2; mi++) {
            int m = wm + mi * 16 + gr;
            uint2 a;
            a = Qs[m * 70 + k0 + gc];           ahi[mi][0] = a.x; alo[mi][0] = a.y;
            a = Qs[(m + 8) * 70 + k0 + gc];     ahi[mi][1] = a.x; alo[mi][1] = a.y;
            a = Qs[m * 70 + k0 + 4 + gc];       ahi[mi][2] = a.x; alo[mi][2] = a.y;
            a = Qs[(m + 8) * 70 + k0 + 4 + gc]; ahi[mi][3] = a.x; alo[mi][3] = a.y;
        }
#pragma unroll
        for (int ni = 0; ni < 8; ni++) {
            int n = wn + ni * 8 + gr;
            uint2 b0 = Ks[n * 70 + k0 + gc];      // (bh0, bl0)
            uint2 b1 = Ks[n * 70 + k0 + 4 + gc];  // (bh1, bl1)
#pragma unroll
            for (int mi = 0; mi < 2; mi++) {
                MMA_TF32(acc[mi][ni], ahi[mi], b0.x, b1.x);
                MMA_TF32(acc[mi][ni], ahi[mi], b0.y, b1.y);
                MMA_TF32(acc[mi][ni], alo[mi], b0.x, b1.x);
            }
        }
    }

    const float scale = 0.125f;
#pragma unroll
    for (int mi = 0; mi < 2; mi++)
#pragma unroll
        for (int ni = 0; ni < 8; ni++) {
            int row = i0 + wm + mi * 16 + gr;
            int col = j0 + wn + ni * 8 + gc * 2;
            float2 v0 = { acc[mi][ni][0] * scale, acc[mi][ni][1] * scale };
            __stcs((float2*)(S + ((size_t)bh * NQ + row) * NK + col), v0);
            float2 v1 = { acc[mi][ni][2] * scale, acc[mi][ni][3] * scale };
            __stcs((float2*)(S + ((size_t)bh * NQ + row + 8) * NK + col), v1);
        }
}

// ---------------------------------------------------------------------------
// Generic 3xTF32 MMA GEMM (NN): C = A @ B (+ bias), ld-parameterized.
// Used for V projection and out-projection (both post-selection safe).
// ---------------------------------------------------------------------------
__global__ void __launch_bounds__(256) gemm_tf32_nn(
    const float* __restrict__ A, const float* __restrict__ Bm,
    const float* __restrict__ bias, float* __restrict__ C,
    int M, int N, int K, int lda, int ldb, int ldc)
{
    __shared__ float As[2][128 * 12];
    __shared__ float Bs[2][128 * 12];
    const int tid  = threadIdx.x;
    const int row0 = blockIdx.y * 128, col0 = blockIdx.x * 128;
    const int a_row = tid >> 1, a_k = (tid & 1) * 4;
    const int b_k   = tid >> 5, b_n = (tid & 31) * 4;
    const float* Ap = A  + (size_t)(row0 + a_row) * lda + a_k;
    const float* Bp = Bm + (size_t)b_k * ldb + col0 + b_n;

    {
        float4 a4 = *(const float4*)Ap;
        *(float4*)(As[0] + a_row * 12 + a_k) = a4;
        float4 b4 = *(const float4*)Bp;
        Bs[0][(b_n + 0) * 12 + b_k] = b4.x;
        Bs[0][(b_n + 1) * 12 + b_k] = b4.y;
        Bs[0][(b_n + 2) * 12 + b_k] = b4.z;
        Bs[0][(b_n + 3) * 12 + b_k] = b4.w;
    }
    __syncthreads();

    const int lane = tid & 31, wid = tid >> 5;
    const int wm = (wid & 3) * 32, wn = (wid >> 2) * 64;
    const int gr = lane >> 2, gc = lane & 3;

    float acc[2][8][4];
#pragma unroll
    for (int mi = 0; mi < 2; mi++)
#pragma unroll
        for (int ni = 0; ni < 8; ni++)
#pragma unroll
            for (int q = 0; q < 4; q++) acc[mi][ni][q] = 0.f;

    int buf = 0;
    for (int k0 = 8; k0 <= K; k0 += 8) {
        const bool has = (k0 < K);
        float4 a4, b4;
        if (has) {
            a4 = *(const float4*)(Ap + k0);
            b4 = *(const float4*)(Bp + (size_t)k0 * ldb);
        }
        unsigned ahi[2][4], alo[2][4];
#pragma unroll
        for (int mi = 0; mi < 2; mi++) {
            int m = wm + mi * 16 + gr;
            split_tf32(As[buf][m * 12 + gc],           ahi[mi][0], alo[mi][0]);
            split_tf32(As[buf][(m + 8) * 12 + gc],     ahi[mi][1], alo[mi][1]);
            split_tf32(As[buf][m * 12 + 4 + gc],       ahi[mi][2], alo[mi][2]);
            split_tf32(As[buf][(m + 8) * 12 + 4 + gc], ahi[mi][3], alo[mi][3]);
        }
#pragma unroll
        for (int ni = 0; ni < 8; ni++) {
            int n = wn + ni * 8 + gr;
            unsigned bh0, bl0, bh1, bl1;
            split_tf32(Bs[buf][n * 12 + gc],     bh0, bl0);
            split_tf32(Bs[buf][n * 12 + 4 + gc], bh1, bl1);
#pragma unroll
            for (int mi = 0; mi < 2; mi++) {
                MMA_TF32(acc[mi][ni], ahi[mi], bh0, bh1);
                MMA_TF32(acc[mi][ni], ahi[mi], bl0, bl1);
                MMA_TF32(acc[mi][ni], alo[mi], bh0, bh1);
            }
        }
        if (has) {
            const int nb = buf ^ 1;
            *(float4*)(As[nb] + a_row * 12 + a_k) = a4;
            Bs[nb][(b_n + 0) * 12 + b_k] = b4.x;
            Bs[nb][(b_n + 1) * 12 + b_k] = b4.y;
            Bs[nb][(b_n + 2) * 12 + b_k] = b4.z;
            Bs[nb][(b_n + 3) * 12 + b_k] = b4.w;
            __syncthreads();
            buf = nb;
        }
    }

#pragma unroll
    for (int mi = 0; mi < 2; mi++)
#pragma unroll
        for (int ni = 0; ni < 8; ni++) {
            int row = row0 + wm + mi * 16 + gr;
            int col = col0 + wn + ni * 8 + gc * 2;
            float bx = 0.f, by = 0.f;
            if (bias) { bx = bias[col]; by = bias[col + 1]; }
            float2 v0 = { acc[mi][ni][0] + bx, acc[mi][ni][1] + by };
            *(float2*)(C + (size_t)row * ldc + col) = v0;
            float2 v1 = { acc[mi][ni][2] + bx, acc[mi][ni][3] + by };
            *(float2*)(C + (size_t)(row + 8) * ldc + col) = v1;
        }
}

// ---------------------------------------------------------------------------
// Per query row: exact top-64 (R8 algorithm, unchanged except V addressing).
// Threshold via per-warp shuffle-bitonic sort (t_hat = min over warps of each
// warp's 16th-largest thread-max => >=64 values >= t_hat => exact prefilter).
// Compact candidates, exact rank-select on composite keys (value desc, index
// asc == jax.lax.top_k ties), softmax, sparse PV.
// ---------------------------------------------------------------------------
__global__ void __launch_bounds__(128, 12) topk_attn(
    const float* __restrict__ S, const float* __restrict__ V, float* __restrict__ O)
{
    const int r  = blockIdx.x;
    const int bh = r >> 11, i = r & 2047;
    const int b  = bh >> 3, h = bh & 7;
    const float* srow = S + (size_t)r * NK;

    __shared__ __align__(16) unsigned long long ckey[2049];  // worst-case + pad
    __shared__ float warpthr[4];
    __shared__ float selv[64];
    __shared__ int   seli[64];
    __shared__ float s_wsum;
    __shared__ int   s_ncand;
    __shared__ float w[64];
    __shared__ float part[64];

    const int tid = threadIdx.x;
    const int lane = tid & 31, wrp = tid >> 5;
    if (tid == 0) s_ncand = 0;

    float vals[16];
#pragma unroll
    for (int t = 0; t < 4; t++) {
        float4 v = __ldcs((const float4*)srow + tid + t * 128);
        vals[t * 4 + 0] = v.x; vals[t * 4 + 1] = v.y;
        vals[t * 4 + 2] = v.z; vals[t * 4 + 3] = v.w;
    }
    float tmax = vals[0];
#pragma unroll
    for (int t = 1; t < 16; t++) tmax = fmaxf(tmax, vals[t]);

    // warp bitonic sort (descending) of the 32 thread-maxes
    {
        float v = tmax;
#pragma unroll
        for (int k = 2; k <= 32; k <<= 1) {
#pragma unroll
            for (int j = k >> 1; j > 0; j >>= 1) {
                float o = __shfl_xor_sync(0xffffffffu, v, j);
                bool ascBlock = ((lane & k) != 0);
                bool upper    = ((lane & j) != 0);
                v = (upper == ascBlock) ? fmaxf(v, o) : fminf(v, o);
            }
        }
        float t_w = __shfl_sync(0xffffffffu, v, 15);   // 16th largest in warp
        if (lane == 0) warpthr[wrp] = t_w;
    }
    __syncthreads();
    const float thr = fminf(fminf(warpthr[0], warpthr[1]),
                            fminf(warpthr[2], warpthr[3]));

    // warp-aggregated compaction of candidates (v >= thr)
#pragma unroll
    for (int t = 0; t < 16; t++) {
        bool p = (vals[t] >= thr);
        unsigned ball = __ballot_sync(0xffffffffu, p);
        if (ball) {
            int base;
            if (lane == 0) base = atomicAdd(&s_ncand, __popc(ball));
            base = __shfl_sync(0xffffffffu, base, 0);
            if (p) {
                int off = __popc(ball & ((1u << lane) - 1u));
                int j = (tid + (t >> 2) * 128) * 4 + (t & 3);
                ckey[base + off] =
                    ((unsigned long long)fkey(vals[t]) << 32) | (unsigned)(2047 - j);
            }
        }
    }
    __syncthreads();
    const int nc = s_ncand;
    if (tid == 0) ckey[nc] = 0ull;    // pad so paired reads are safe
    __syncthreads();

    // exact top-64 by rank over candidates (vectorized smem reads)
    for (int c = tid; c < nc; c += 128) {
        unsigned long long k = ckey[c];
        int rk = 0;
        for (int o = 0; o < nc; o += 2) {
            ulonglong2 kk = *(const ulonglong2*)&ckey[o];
            rk += (kk.x > k) + (kk.y > k);
        }
        if (rk < KKEEP) {
            selv[rk] = unfkey((unsigned)(k >> 32));
            seli[rk] = 2047 - (int)(k & 0xffffffffu);
        }
    }
    __syncthreads();   // selv[0] = row max

    if (tid < 64) w[tid] = expf(selv[tid] - selv[0]);
    __syncthreads();
    if (tid < 32) {
        float s = w[tid] + w[tid + 32];
#pragma unroll
        for (int off = 16; off; off >>= 1)
            s += __shfl_xor_sync(0xffffffffu, s, off);
        if (tid == 0) s_wsum = s;
    }
    __syncthreads();

    const int g = tid >> 6, d = tid & 63;
    const float* Vbase = V + (size_t)b * NK * INNER + h * HD + d;
    float acc = 0.f;
#pragma unroll 4
    for (int jj = 0; jj < 32; jj++) {
        int j = g * 32 + jj;
        acc += w[j] * Vbase[(size_t)seli[j] * INNER];
    }
    if (g == 1) part[d] = acc;
    __syncthreads();
    if (g == 0) {
        float o = (acc + part[d]) / s_wsum;
        O[((size_t)(b * NQ + i)) * INNER + h * HD + d] = o;
    }
}

// ---------------------------------------------------------------------------
extern "C" void kernel_launch(void* const* d_in, const int* in_sizes, int n_in,
                              void* d_out, int out_size)
{
    const float* x    = (const float*)d_in[0];
    const float* ctx  = (const float*)d_in[1];
    const float* Wq   = (const float*)d_in[2];
    const float* Wkv  = (const float*)d_in[3];
    const float* Wout = (const float*)d_in[4];
    const float* bout = (const float*)d_in[5];
    float* out = (float*)d_out;

    uint2 *pQp, *pKp;
    float *pV, *pS, *pO;
    cudaGetSymbolAddress((void**)&pQp, g_Qp);
    cudaGetSymbolAddress((void**)&pKp, g_Kp);
    cudaGetSymbolAddress((void**)&pV,  g_V);
    cudaGetSymbolAddress((void**)&pS,  g_S);
    cudaGetSymbolAddress((void**)&pO,  g_O);

    const int simSmem = 2 * 128 * 70 * 8;   // 143360 B (packed u64 tiles)
    cudaFuncSetAttribute(sim_tf32p, cudaFuncAttributeMaxDynamicSharedMemorySize, simSmem);

    dim3 blk(256);
    // Q = x @ Wq   (fp32 accum; epilogue writes packed tf32 hi/lo)
    sgemm_nn_sp<<<dim3(INNER / 128, BATCH * NQ / 128), blk>>>(
        x, Wq, pQp, BATCH * NQ, INNER, DQ, DQ, INNER, INNER);
    // K-half: ctx @ Wkv[:, 0:512]  (fp32 accum; packed epilogue)
    sgemm_nn_sp<<<dim3(INNER / 128, BATCH * NK / 128), blk>>>(
        ctx, Wkv, pKp, BATCH * NK, INNER, DQ, DQ, 2 * INNER, INNER);
    // V-half: ctx @ Wkv[:, 512:1024]  (3xTF32; post-selection, safe)
    gemm_tf32_nn<<<dim3(INNER / 128, BATCH * NK / 128), blk>>>(
        ctx, Wkv + INNER, nullptr, pV,
        BATCH * NK, INNER, DQ, DQ, 2 * INNER, INNER);
    // sim = Q @ K^T * scale (3-term TF32 on pre-split operands; S bits == R8)
    sim_tf32p<<<dim3(NK / 128, NQ / 128, BATCH * NH), blk, simSmem>>>(pQp, pKp, pS);
    // exact top-64 + softmax + sparse PV
    topk_attn<<<dim3(BATCH * NH * NQ), dim3(128)>>>(pS, pV, pO);
    // out = O @ Wout + bout (3xTF32)
    gemm_tf32_nn<<<dim3(DQ / 128, BATCH * NQ / 128), blk>>>(
        pO, Wout, bout, out, BATCH * NQ, DQ, INNER, INNER, DQ, DQ);
}

// round 12
// speedup vs baseline: 3.2073x; 1.2226x over previous
#include <cuda_runtime.h>

#define BATCH 4
#define NQ    2048
#define NK    2048
#define DQ    1024
#define NH    8
#define HD    64
#define INNER 512
#define KKEEP 64

// Scratch (device globals; allocation-free contract)
__device__ float g_Q [BATCH * NQ * INNER];          // 16.8 MB
__device__ float g_KV[BATCH * NK * 2 * INNER];      // 33.5 MB  (K: cols 0..511, V: 512..1023)
__device__ float g_S [134217728];                   // 512 MB   sim [B*H][NQ][NK]
__device__ float g_O [BATCH * NQ * INNER];          // 16.8 MB

// ---- tf32 split helpers + warp MMA --------------------------------------------
__device__ __forceinline__ void split_tf32(float v, unsigned& hi, unsigned& lo) {
    asm("cvt.rna.tf32.f32 %0, %1;" : "=r"(hi) : "f"(v));
    float l = v - __uint_as_float(hi);
    asm("cvt.rna.tf32.f32 %0, %1;" : "=r"(lo) : "f"(l));
}

#define MMA_TF32(c, a, b0, b1) \
    asm("mma.sync.aligned.m16n8k8.row.col.f32.tf32.tf32.f32 " \
        "{%0,%1,%2,%3}, {%4,%5,%6,%7}, {%8,%9}, {%0,%1,%2,%3};" \
        : "+f"((c)[0]), "+f"((c)[1]), "+f"((c)[2]), "+f"((c)[3]) \
        : "r"((a)[0]), "r"((a)[1]), "r"((a)[2]), "r"((a)[3]), "r"(b0), "r"(b1))

__device__ __forceinline__ unsigned fkey(float f) {
    unsigned u = __float_as_uint(f);
    return (u & 0x80000000u) ? ~u : (u | 0x80000000u);
}
__device__ __forceinline__ float unfkey(unsigned k) {
    unsigned u = (k & 0x80000000u) ? (k & 0x7fffffffu) : ~k;
    return __uint_as_float(u);
}

// ---------------------------------------------------------------------------
// fp32 SGEMM (NN), double-buffered, ld-parameterized (Q and K projections).
// ---------------------------------------------------------------------------
__global__ void __launch_bounds__(256) sgemm_nn(
    const float* __restrict__ A, const float* __restrict__ Bm,
    float* __restrict__ C, int M, int N, int K, int lda, int ldb, int ldc)
{
    __shared__ float As[2][8][128];
    __shared__ float Bs[2][8][128];
    const int tid  = threadIdx.x;
    const int row0 = blockIdx.y * 128, col0 = blockIdx.x * 128;
    const int tx   = tid & 15, ty = tid >> 4;
    const int a_row = tid >> 1, a_k = (tid & 1) * 4;
    const int b_k   = tid >> 5, b_col = (tid & 31) * 4;
    const float* Ap = A  + (size_t)(row0 + a_row) * lda + a_k;
    const float* Bp = Bm + (size_t)b_k * ldb + col0 + b_col;

    float acc[8][8];
#pragma unroll
    for (int i = 0; i < 8; i++)
#pragma unroll
        for (int j = 0; j < 8; j++) acc[i][j] = 0.f;

    {
        float4 av = *(const float4*)Ap;
        float4 bv = *(const float4*)Bp;
        As[0][a_k + 0][a_row] = av.x;
        As[0][a_k + 1][a_row] = av.y;
        As[0][a_k + 2][a_row] = av.z;
        As[0][a_k + 3][a_row] = av.w;
        *(float4*)&Bs[0][b_k][b_col] = bv;
    }
    __syncthreads();

    int buf = 0;
    for (int k0 = 8; k0 <= K; k0 += 8) {
        const bool has = (k0 < K);
        float4 av, bv;
        if (has) {
            av = *(const float4*)(Ap + k0);
            bv = *(const float4*)(Bp + (size_t)k0 * ldb);
        }
#pragma unroll
        for (int kk = 0; kk < 8; kk++) {
            float af[8], bf[8];
            *(float4*)&af[0] = *(const float4*)&As[buf][kk][ty * 4];
            *(float4*)&af[4] = *(const float4*)&As[buf][kk][ty * 4 + 64];
            *(float4*)&bf[0] = *(const float4*)&Bs[buf][kk][tx * 4];
            *(float4*)&bf[4] = *(const float4*)&Bs[buf][kk][tx * 4 + 64];
#pragma unroll
            for (int i = 0; i < 8; i++)
#pragma unroll
                for (int j = 0; j < 8; j++)
                    acc[i][j] += af[i] * bf[j];
        }
        if (has) {
            const int nb = buf ^ 1;
            As[nb][a_k + 0][a_row] = av.x;
            As[nb][a_k + 1][a_row] = av.y;
            As[nb][a_k + 2][a_row] = av.z;
            As[nb][a_k + 3][a_row] = av.w;
            *(float4*)&Bs[nb][b_k][b_col] = bv;
            __syncthreads();
            buf = nb;
        }
    }

#pragma unroll
    for (int ih = 0; ih < 2; ih++)
#pragma unroll
        for (int ii = 0; ii < 4; ii++) {
            int row = row0 + ty * 4 + ih * 64 + ii;
            float* Cp = C + (size_t)row * ldc + col0;
#pragma unroll
            for (int jh = 0; jh < 2; jh++) {
                int c = tx * 4 + jh * 64;
                float4 v;
                v.x = acc[ih * 4 + ii][jh * 4 + 0];
                v.y = acc[ih * 4 + ii][jh * 4 + 1];
                v.z = acc[ih * 4 + ii][jh * 4 + 2];
                v.w = acc[ih * 4 + ii][jh * 4 + 3];
                *(float4*)(Cp + c) = v;
            }
        }
}

// ---------------------------------------------------------------------------
// sim via 3-term TF32 MMA (NT): S = 0.125 * Q_h . K_h^T
// 128x128 tile; 512 threads, 16 warps, warp tile 32x32 (acc 32 regs ->
// __launch_bounds__(512,2) -> 2 blocks/SM = 32 warps resident).
// Per-output k-order and 3-term order identical to R8 -> bitwise-identical S.
// ---------------------------------------------------------------------------
__global__ void __launch_bounds__(512, 2) sim_tf32(
    const float* __restrict__ Q, const float* __restrict__ KV, float* __restrict__ S)
{
    extern __shared__ float sm[];
    float* Qs = sm;              // [128][68]
    float* Ks = sm + 128 * 68;   // [128][68]
    const int bh = blockIdx.z, b = bh >> 3, h = bh & 7;
    const int i0 = blockIdx.y * 128, j0 = blockIdx.x * 128;
    const int tid = threadIdx.x;

#pragma unroll
    for (int l = 0; l < 4; l++) {
        int idx = tid + l * 512;                 // 0..2047
        int row = idx >> 4, k0 = (idx & 15) * 4;
        float4 q4 = *(const float4*)(Q  + (size_t)(b * NQ + i0 + row) * INNER       + h * HD + k0);
        *(float4*)(Qs + row * 68 + k0) = q4;
        float4 k4 = *(const float4*)(KV + (size_t)(b * NK + j0 + row) * (2 * INNER) + h * HD + k0);
        *(float4*)(Ks + row * 68 + k0) = k4;
    }
    __syncthreads();

    const int lane = tid & 31, wid = tid >> 5;   // wid 0..15
    const int wm = (wid & 3) * 32, wn = (wid >> 2) * 32;
    const int gr = lane >> 2, gc = lane & 3;

    float acc[2][4][4];
#pragma unroll
    for (int mi = 0; mi < 2; mi++)
#pragma unroll
        for (int ni = 0; ni < 4; ni++)
#pragma unroll
            for (int q = 0; q < 4; q++) acc[mi][ni][q] = 0.f;

#pragma unroll
    for (int k0 = 0; k0 < 64; k0 += 8) {
        unsigned ahi[2][4], alo[2][4];
#pragma unroll
        for (int mi = 0; mi < 2; mi++) {
            int m = wm + mi * 16 + gr;
            split_tf32(Qs[m * 68 + k0 + gc],           ahi[mi][0], alo[mi][0]);
            split_tf32(Qs[(m + 8) * 68 + k0 + gc],     ahi[mi][1], alo[mi][1]);
            split_tf32(Qs[m * 68 + k0 + 4 + gc],       ahi[mi][2], alo[mi][2]);
            split_tf32(Qs[(m + 8) * 68 + k0 + 4 + gc], ahi[mi][3], alo[mi][3]);
        }
#pragma unroll
        for (int ni = 0; ni < 4; ni++) {
            int n = wn + ni * 8 + gr;
            unsigned bh0, bl0, bh1, bl1;
            split_tf32(Ks[n * 68 + k0 + gc],     bh0, bl0);
            split_tf32(Ks[n * 68 + k0 + 4 + gc], bh1, bl1);
#pragma unroll
            for (int mi = 0; mi < 2; mi++) {
                MMA_TF32(acc[mi][ni], ahi[mi], bh0, bh1);
                MMA_TF32(acc[mi][ni], ahi[mi], bl0, bl1);
                MMA_TF32(acc[mi][ni], alo[mi], bh0, bh1);
            }
        }
    }

    const float scale = 0.125f;
#pragma unroll
    for (int mi = 0; mi < 2; mi++)
#pragma unroll
        for (int ni = 0; ni < 4; ni++) {
            int row = i0 + wm + mi * 16 + gr;
            int col = j0 + wn + ni * 8 + gc * 2;
            float2 v0 = { acc[mi][ni][0] * scale, acc[mi][ni][1] * scale };
            __stcs((float2*)(S + ((size_t)bh * NQ + row) * NK + col), v0);
            float2 v1 = { acc[mi][ni][2] * scale, acc[mi][ni][3] * scale };
            __stcs((float2*)(S + ((size_t)bh * NQ + row + 8) * NK + col), v1);
        }
}

// ---------------------------------------------------------------------------
// Generic 3xTF32 MMA GEMM (NN): C = A @ B (+ bias), ld-parameterized.
// Used for V-half projection and out-projection (both post-selection safe).
// ---------------------------------------------------------------------------
__global__ void __launch_bounds__(256) gemm_tf32_nn(
    const float* __restrict__ A, const float* __restrict__ Bm,
    const float* __restrict__ bias, float* __restrict__ C,
    int M, int N, int K, int lda, int ldb, int ldc)
{
    __shared__ float As[2][128 * 12];
    __shared__ float Bs[2][128 * 12];
    const int tid  = threadIdx.x;
    const int row0 = blockIdx.y * 128, col0 = blockIdx.x * 128;
    const int a_row = tid >> 1, a_k = (tid & 1) * 4;
    const int b_k   = tid >> 5, b_n = (tid & 31) * 4;
    const float* Ap = A  + (size_t)(row0 + a_row) * lda + a_k;
    const float* Bp = Bm + (size_t)b_k * ldb + col0 + b_n;

    {
        float4 a4 = *(const float4*)Ap;
        *(float4*)(As[0] + a_row * 12 + a_k) = a4;
        float4 b4 = *(const float4*)Bp;
        Bs[0][(b_n + 0) * 12 + b_k] = b4.x;
        Bs[0][(b_n + 1) * 12 + b_k] = b4.y;
        Bs[0][(b_n + 2) * 12 + b_k] = b4.z;
        Bs[0][(b_n + 3) * 12 + b_k] = b4.w;
    }
    __syncthreads();

    const int lane = tid & 31, wid = tid >> 5;
    const int wm = (wid & 3) * 32, wn = (wid >> 2) * 64;
    const int gr = lane >> 2, gc = lane & 3;

    float acc[2][8][4];
#pragma unroll
    for (int mi = 0; mi < 2; mi++)
#pragma unroll
        for (int ni = 0; ni < 8; ni++)
#pragma unroll
            for (int q = 0; q < 4; q++) acc[mi][ni][q] = 0.f;

    int buf = 0;
    for (int k0 = 8; k0 <= K; k0 += 8) {
        const bool has = (k0 < K);
        float4 a4, b4;
        if (has) {
            a4 = *(const float4*)(Ap + k0);
            b4 = *(const float4*)(Bp + (size_t)k0 * ldb);
        }
        unsigned ahi[2][4], alo[2][4];
#pragma unroll
        for (int mi = 0; mi < 2; mi++) {
            int m = wm + mi * 16 + gr;
            split_tf32(As[buf][m * 12 + gc],           ahi[mi][0], alo[mi][0]);
            split_tf32(As[buf][(m + 8) * 12 + gc],     ahi[mi][1], alo[mi][1]);
            split_tf32(As[buf][m * 12 + 4 + gc],       ahi[mi][2], alo[mi][2]);
            split_tf32(As[buf][(m + 8) * 12 + 4 + gc], ahi[mi][3], alo[mi][3]);
        }
#pragma unroll
        for (int ni = 0; ni < 8; ni++) {
            int n = wn + ni * 8 + gr;
            unsigned bh0, bl0, bh1, bl1;
            split_tf32(Bs[buf][n * 12 + gc],     bh0, bl0);
            split_tf32(Bs[buf][n * 12 + 4 + gc], bh1, bl1);
#pragma unroll
            for (int mi = 0; mi < 2; mi++) {
                MMA_TF32(acc[mi][ni], ahi[mi], bh0, bh1);
                MMA_TF32(acc[mi][ni], ahi[mi], bl0, bl1);
                MMA_TF32(acc[mi][ni], alo[mi], bh0, bh1);
            }
        }
        if (has) {
            const int nb = buf ^ 1;
            *(float4*)(As[nb] + a_row * 12 + a_k) = a4;
            Bs[nb][(b_n + 0) * 12 + b_k] = b4.x;
            Bs[nb][(b_n + 1) * 12 + b_k] = b4.y;
            Bs[nb][(b_n + 2) * 12 + b_k] = b4.z;
            Bs[nb][(b_n + 3) * 12 + b_k] = b4.w;
            __syncthreads();
            buf = nb;
        }
    }

#pragma unroll
    for (int mi = 0; mi < 2; mi++)
#pragma unroll
        for (int ni = 0; ni < 8; ni++) {
            int row = row0 + wm + mi * 16 + gr;
            int col = col0 + wn + ni * 8 + gc * 2;
            float bx = 0.f, by = 0.f;
            if (bias) { bx = bias[col]; by = bias[col + 1]; }
            float2 v0 = { acc[mi][ni][0] + bx, acc[mi][ni][1] + by };
            *(float2*)(C + (size_t)row * ldc + col) = v0;
            float2 v1 = { acc[mi][ni][2] + bx, acc[mi][ni][3] + by };
            *(float2*)(C + (size_t)(row + 8) * ldc + col) = v1;
        }
}

// ---------------------------------------------------------------------------
// Per query row: exact top-64.
//  Threshold: per-warp shuffle-bitonic sort of 32 thread-maxes (desc);
//  t_hat = min over warps of warp's 16th-largest (exact prefilter: >=64
//  values >= t_hat => all true top-64 are candidates).
//  Compaction: warp inclusive scan + one atomic per warp (order-free;
//  rank-select is order-independent).  Exact rank-select on composite keys
//  (value desc, index asc == jax.lax.top_k ties), softmax, sparse PV.
// ---------------------------------------------------------------------------
__global__ void __launch_bounds__(128, 12) topk_attn(
    const float* __restrict__ S, const float* __restrict__ KV, float* __restrict__ O)
{
    const int r  = blockIdx.x;
    const int bh = r >> 11, i = r & 2047;
    const int b  = bh >> 3, h = bh & 7;
    const float* srow = S + (size_t)r * NK;

    __shared__ __align__(16) unsigned long long ckey[2049];  // worst-case + pad
    __shared__ float warpthr[4];
    __shared__ float selv[64];
    __shared__ int   seli[64];
    __shared__ float s_wsum;
    __shared__ int   s_ncand;
    __shared__ float w[64];
    __shared__ float part[64];

    const int tid = threadIdx.x;
    const int lane = tid & 31, wrp = tid >> 5;
    if (tid == 0) s_ncand = 0;

    float vals[16];
#pragma unroll
    for (int t = 0; t < 4; t++) {
        float4 v = __ldcs((const float4*)srow + tid + t * 128);
        vals[t * 4 + 0] = v.x; vals[t * 4 + 1] = v.y;
        vals[t * 4 + 2] = v.z; vals[t * 4 + 3] = v.w;
    }
    float tmax = vals[0];
#pragma unroll
    for (int t = 1; t < 16; t++) tmax = fmaxf(tmax, vals[t]);

    // warp bitonic sort (descending) of the 32 thread-maxes
    {
        float v = tmax;
#pragma unroll
        for (int k = 2; k <= 32; k <<= 1) {
#pragma unroll
            for (int j = k >> 1; j > 0; j >>= 1) {
                float o = __shfl_xor_sync(0xffffffffu, v, j);
                bool ascBlock = ((lane & k) != 0);
                bool upper    = ((lane & j) != 0);
                v = (upper == ascBlock) ? fmaxf(v, o) : fminf(v, o);
            }
        }
        float t_w = __shfl_sync(0xffffffffu, v, 15);   // 16th largest in warp
        if (lane == 0) warpthr[wrp] = t_w;
    }
    __syncthreads();
    const float thr = fminf(fminf(warpthr[0], warpthr[1]),
                            fminf(warpthr[2], warpthr[3]));

    // scan-based compaction of candidates (v >= thr)
    {
        int cnt = 0;
#pragma unroll
        for (int t = 0; t < 16; t++) cnt += (vals[t] >= thr) ? 1 : 0;
        int pfx = cnt;
#pragma unroll
        for (int off = 1; off < 32; off <<= 1) {
            int o = __shfl_up_sync(0xffffffffu, pfx, off);
            if (lane >= off) pfx += o;
        }
        int wbase = 0;
        if (lane == 31) wbase = atomicAdd(&s_ncand, pfx);
        wbase = __shfl_sync(0xffffffffu, wbase, 31);
        int p = wbase + pfx - cnt;
#pragma unroll
        for (int t = 0; t < 16; t++) {
            if (vals[t] >= thr) {
                int j = (tid + (t >> 2) * 128) * 4 + (t & 3);
                ckey[p++] =
                    ((unsigned long long)fkey(vals[t]) << 32) | (unsigned)(2047 - j);
            }
        }
    }
    __syncthreads();
    const int nc = s_ncand;
    if (tid == 0) ckey[nc] = 0ull;    // pad so paired reads are safe
    __syncthreads();

    // exact top-64 by rank over candidates (vectorized smem reads)
    for (int c = tid; c < nc; c += 128) {
        unsigned long long k = ckey[c];
        int rk = 0;
        for (int o = 0; o < nc; o += 2) {
            ulonglong2 kk = *(const ulonglong2*)&ckey[o];
            rk += (kk.x > k) + (kk.y > k);
        }
        if (rk < KKEEP) {
            selv[rk] = unfkey((unsigned)(k >> 32));
            seli[rk] = 2047 - (int)(k & 0xffffffffu);
        }
    }
    __syncthreads();   // selv[0] = row max

    if (tid < 64) w[tid] = expf(selv[tid] - selv[0]);
    __syncthreads();
    if (tid < 32) {
        float s = w[tid] + w[tid + 32];
#pragma unroll
        for (int off = 16; off; off >>= 1)
            s += __shfl_xor_sync(0xffffffffu, s, off);
        if (tid == 0) s_wsum = s;
    }
    __syncthreads();

    const int g = tid >> 6, d = tid & 63;
    const float* Vbase = KV + (size_t)b * NK * (2 * INNER) + INNER + h * HD + d;
    float acc = 0.f;
#pragma unroll 4
    for (int jj = 0; jj < 32; jj++) {
        int j = g * 32 + jj;
        acc += w[j] * Vbase[(size_t)seli[j] * (2 * INNER)];
    }
    if (g == 1) part[d] = acc;
    __syncthreads();
    if (g == 0) {
        float o = (acc + part[d]) / s_wsum;
        O[((size_t)(b * NQ + i)) * INNER + h * HD + d] = o;
    }
}

// ---------------------------------------------------------------------------
extern "C" void kernel_launch(void* const* d_in, const int* in_sizes, int n_in,
                              void* d_out, int out_size)
{
    const float* x    = (const float*)d_in[0];
    const float* ctx  = (const float*)d_in[1];
    const float* Wq   = (const float*)d_in[2];
    const float* Wkv  = (const float*)d_in[3];
    const float* Wout = (const float*)d_in[4];
    const float* bout = (const float*)d_in[5];
    float* out = (float*)d_out;

    float *pQ, *pKV, *pS, *pO;
    cudaGetSymbolAddress((void**)&pQ,  g_Q);
    cudaGetSymbolAddress((void**)&pKV, g_KV);
    cudaGetSymbolAddress((void**)&pS,  g_S);
    cudaGetSymbolAddress((void**)&pO,  g_O);

    const int simSmem = 2 * 128 * 68 * sizeof(float);   // 69632 B
    cudaFuncSetAttribute(sim_tf32, cudaFuncAttributeMaxDynamicSharedMemorySize, simSmem);

    dim3 blk(256);
    // Q = x @ Wq   (fp32; feeds selection)
    sgemm_nn<<<dim3(INNER / 128, BATCH * NQ / 128), blk>>>(
        x, Wq, pQ, BATCH * NQ, INNER, DQ, DQ, INNER, INNER);
    // K-half: ctx @ Wkv[:, 0:512]  (fp32; feeds selection)
    sgemm_nn<<<dim3(INNER / 128, BATCH * NK / 128), blk>>>(
        ctx, Wkv, pKV, BATCH * NK, INNER, DQ, DQ, 2 * INNER, 2 * INNER);
    // V-half: ctx @ Wkv[:, 512:1024]  (3xTF32; post-selection, safe)
    gemm_tf32_nn<<<dim3(INNER / 128, BATCH * NK / 128), blk>>>(
        ctx, Wkv + INNER, nullptr, pKV + INNER,
        BATCH * NK, INNER, DQ, DQ, 2 * INNER, 2 * INNER);
    // sim = Q @ K^T * scale (3-term TF32; 512 threads, 2 blocks/SM)
    sim_tf32<<<dim3(NK / 128, NQ / 128, BATCH * NH), dim3(512), simSmem>>>(pQ, pKV, pS);
    // exact top-64 + softmax + sparse PV
    topk_attn<<<dim3(BATCH * NH * NQ), dim3(128)>>>(pS, pKV, pO);
    // out = O @ Wout + bout (3xTF32)
    gemm_tf32_nn<<<dim3(DQ / 128, BATCH * NQ / 128), blk>>>(
        pO, Wout, bout, out, BATCH * NQ, DQ, INNER, INNER, DQ, DQ);
}

// round 13
// speedup vs baseline: 3.2440x; 1.0114x over previous
#include <cuda_runtime.h>

#define BATCH 4
#define NQ    2048
#define NK    2048
#define DQ    1024
#define NH    8
#define HD    64
#define INNER 512
#define KKEEP 64
#define CCAP  512

// Scratch (device globals; allocation-free contract)
__device__ float g_Q [BATCH * NQ * INNER];          // 16.8 MB
__device__ float g_KV[BATCH * NK * 2 * INNER];      // 33.5 MB  (K: cols 0..511, V: 512..1023)
__device__ float g_S [134217728];                   // 512 MB   sim [B*H][NQ][NK]
__device__ float g_O [BATCH * NQ * INNER];          // 16.8 MB

// ---- tf32 split helpers + warp MMA --------------------------------------------
__device__ __forceinline__ void split_tf32(float v, unsigned& hi, unsigned& lo) {
    asm("cvt.rna.tf32.f32 %0, %1;" : "=r"(hi) : "f"(v));
    float l = v - __uint_as_float(hi);
    asm("cvt.rna.tf32.f32 %0, %1;" : "=r"(lo) : "f"(l));
}

#define MMA_TF32(c, a, b0, b1) \
    asm("mma.sync.aligned.m16n8k8.row.col.f32.tf32.tf32.f32 " \
        "{%0,%1,%2,%3}, {%4,%5,%6,%7}, {%8,%9}, {%0,%1,%2,%3};" \
        : "+f"((c)[0]), "+f"((c)[1]), "+f"((c)[2]), "+f"((c)[3]) \
        : "r"((a)[0]), "r"((a)[1]), "r"((a)[2]), "r"((a)[3]), "r"(b0), "r"(b1))

__device__ __forceinline__ unsigned fkey(float f) {
    unsigned u = __float_as_uint(f);
    return (u & 0x80000000u) ? ~u : (u | 0x80000000u);
}
__device__ __forceinline__ float unfkey(unsigned k) {
    unsigned u = (k & 0x80000000u) ? (k & 0x7fffffffu) : ~k;
    return __uint_as_float(u);
}

// ---------------------------------------------------------------------------
// fp32 SGEMM (NN), double-buffered, ld-parameterized (Q and K projections).
// ---------------------------------------------------------------------------
__global__ void __launch_bounds__(256) sgemm_nn(
    const float* __restrict__ A, const float* __restrict__ Bm,
    float* __restrict__ C, int M, int N, int K, int lda, int ldb, int ldc)
{
    __shared__ float As[2][8][128];
    __shared__ float Bs[2][8][128];
    const int tid  = threadIdx.x;
    const int row0 = blockIdx.y * 128, col0 = blockIdx.x * 128;
    const int tx   = tid & 15, ty = tid >> 4;
    const int a_row = tid >> 1, a_k = (tid & 1) * 4;
    const int b_k   = tid >> 5, b_col = (tid & 31) * 4;
    const float* Ap = A  + (size_t)(row0 + a_row) * lda + a_k;
    const float* Bp = Bm + (size_t)b_k * ldb + col0 + b_col;

    float acc[8][8];
#pragma unroll
    for (int i = 0; i < 8; i++)
#pragma unroll
        for (int j = 0; j < 8; j++) acc[i][j] = 0.f;

    {
        float4 av = *(const float4*)Ap;
        float4 bv = *(const float4*)Bp;
        As[0][a_k + 0][a_row] = av.x;
        As[0][a_k + 1][a_row] = av.y;
        As[0][a_k + 2][a_row] = av.z;
        As[0][a_k + 3][a_row] = av.w;
        *(float4*)&Bs[0][b_k][b_col] = bv;
    }
    __syncthreads();

    int buf = 0;
    for (int k0 = 8; k0 <= K; k0 += 8) {
        const bool has = (k0 < K);
        float4 av, bv;
        if (has) {
            av = *(const float4*)(Ap + k0);
            bv = *(const float4*)(Bp + (size_t)k0 * ldb);
        }
#pragma unroll
        for (int kk = 0; kk < 8; kk++) {
            float af[8], bf[8];
            *(float4*)&af[0] = *(const float4*)&As[buf][kk][ty * 4];
            *(float4*)&af[4] = *(const float4*)&As[buf][kk][ty * 4 + 64];
            *(float4*)&bf[0] = *(const float4*)&Bs[buf][kk][tx * 4];
            *(float4*)&bf[4] = *(const float4*)&Bs[buf][kk][tx * 4 + 64];
#pragma unroll
            for (int i = 0; i < 8; i++)
#pragma unroll
                for (int j = 0; j < 8; j++)
                    acc[i][j] += af[i] * bf[j];
        }
        if (has) {
            const int nb = buf ^ 1;
            As[nb][a_k + 0][a_row] = av.x;
            As[nb][a_k + 1][a_row] = av.y;
            As[nb][a_k + 2][a_row] = av.z;
            As[nb][a_k + 3][a_row] = av.w;
            *(float4*)&Bs[nb][b_k][b_col] = bv;
            __syncthreads();
            buf = nb;
        }
    }

#pragma unroll
    for (int ih = 0; ih < 2; ih++)
#pragma unroll
        for (int ii = 0; ii < 4; ii++) {
            int row = row0 + ty * 4 + ih * 64 + ii;
            float* Cp = C + (size_t)row * ldc + col0;
#pragma unroll
            for (int jh = 0; jh < 2; jh++) {
                int c = tx * 4 + jh * 64;
                float4 v;
                v.x = acc[ih * 4 + ii][jh * 4 + 0];
                v.y = acc[ih * 4 + ii][jh * 4 + 1];
                v.z = acc[ih * 4 + ii][jh * 4 + 2];
                v.w = acc[ih * 4 + ii][jh * 4 + 3];
                *(float4*)(Cp + c) = v;
            }
        }
}

// ---------------------------------------------------------------------------
// sim via 3-term TF32 MMA (NT): S = 0.125 * Q_h . K_h^T
// 128x128 tile; 512 threads, 16 warps, warp tile 32x32, 2 blocks/SM.
// (unchanged from R12 best)
// ---------------------------------------------------------------------------
__global__ void __launch_bounds__(512, 2) sim_tf32(
    const float* __restrict__ Q, const float* __restrict__ KV, float* __restrict__ S)
{
    extern __shared__ float sm[];
    float* Qs = sm;              // [128][68]
    float* Ks = sm + 128 * 68;   // [128][68]
    const int bh = blockIdx.z, b = bh >> 3, h = bh & 7;
    const int i0 = blockIdx.y * 128, j0 = blockIdx.x * 128;
    const int tid = threadIdx.x;

#pragma unroll
    for (int l = 0; l < 4; l++) {
        int idx = tid + l * 512;                 // 0..2047
        int row = idx >> 4, k0 = (idx & 15) * 4;
        float4 q4 = *(const float4*)(Q  + (size_t)(b * NQ + i0 + row) * INNER       + h * HD + k0);
        *(float4*)(Qs + row * 68 + k0) = q4;
        float4 k4 = *(const float4*)(KV + (size_t)(b * NK + j0 + row) * (2 * INNER) + h * HD + k0);
        *(float4*)(Ks + row * 68 + k0) = k4;
    }
    __syncthreads();

    const int lane = tid & 31, wid = tid >> 5;   // wid 0..15
    const int wm = (wid & 3) * 32, wn = (wid >> 2) * 32;
    const int gr = lane >> 2, gc = lane & 3;

    float acc[2][4][4];
#pragma unroll
    for (int mi = 0; mi < 2; mi++)
#pragma unroll
        for (int ni = 0; ni < 4; ni++)
#pragma unroll
            for (int q = 0; q < 4; q++) acc[mi][ni][q] = 0.f;

#pragma unroll
    for (int k0 = 0; k0 < 64; k0 += 8) {
        unsigned ahi[2][4], alo[2][4];
#pragma unroll
        for (int mi = 0; mi < 2; mi++) {
            int m = wm + mi * 16 + gr;
            split_tf32(Qs[m * 68 + k0 + gc],           ahi[mi][0], alo[mi][0]);
            split_tf32(Qs[(m + 8) * 68 + k0 + gc],     ahi[mi][1], alo[mi][1]);
            split_tf32(Qs[m * 68 + k0 + 4 + gc],       ahi[mi][2], alo[mi][2]);
            split_tf32(Qs[(m + 8) * 68 + k0 + 4 + gc], ahi[mi][3], alo[mi][3]);
        }
#pragma unroll
        for (int ni = 0; ni < 4; ni++) {
            int n = wn + ni * 8 + gr;
            unsigned bh0, bl0, bh1, bl1;
            split_tf32(Ks[n * 68 + k0 + gc],     bh0, bl0);
            split_tf32(Ks[n * 68 + k0 + 4 + gc], bh1, bl1);
#pragma unroll
            for (int mi = 0; mi < 2; mi++) {
                MMA_TF32(acc[mi][ni], ahi[mi], bh0, bh1);
                MMA_TF32(acc[mi][ni], ahi[mi], bl0, bl1);
                MMA_TF32(acc[mi][ni], alo[mi], bh0, bh1);
            }
        }
    }

    const float scale = 0.125f;
#pragma unroll
    for (int mi = 0; mi < 2; mi++)
#pragma unroll
        for (int ni = 0; ni < 4; ni++) {
            int row = i0 + wm + mi * 16 + gr;
            int col = j0 + wn + ni * 8 + gc * 2;
            float2 v0 = { acc[mi][ni][0] * scale, acc[mi][ni][1] * scale };
            __stcs((float2*)(S + ((size_t)bh * NQ + row) * NK + col), v0);
            float2 v1 = { acc[mi][ni][2] * scale, acc[mi][ni][3] * scale };
            __stcs((float2*)(S + ((size_t)bh * NQ + row + 8) * NK + col), v1);
        }
}

// ---------------------------------------------------------------------------
// Generic 3xTF32 MMA GEMM (NN): C = A @ B (+ bias), ld-parameterized.
// Used for V-half projection and out-projection (both post-selection safe).
// ---------------------------------------------------------------------------
__global__ void __launch_bounds__(256) gemm_tf32_nn(
    const float* __restrict__ A, const float* __restrict__ Bm,
    const float* __restrict__ bias, float* __restrict__ C,
    int M, int N, int K, int lda, int ldb, int ldc)
{
    __shared__ float As[2][128 * 12];
    __shared__ float Bs[2][128 * 12];
    const int tid  = threadIdx.x;
    const int row0 = blockIdx.y * 128, col0 = blockIdx.x * 128;
    const int a_row = tid >> 1, a_k = (tid & 1) * 4;
    const int b_k   = tid >> 5, b_n = (tid & 31) * 4;
    const float* Ap = A  + (size_t)(row0 + a_row) * lda + a_k;
    const float* Bp = Bm + (size_t)b_k * ldb + col0 + b_n;

    {
        float4 a4 = *(const float4*)Ap;
        *(float4*)(As[0] + a_row * 12 + a_k) = a4;
        float4 b4 = *(const float4*)Bp;
        Bs[0][(b_n + 0) * 12 + b_k] = b4.x;
        Bs[0][(b_n + 1) * 12 + b_k] = b4.y;
        Bs[0][(b_n + 2) * 12 + b_k] = b4.z;
        Bs[0][(b_n + 3) * 12 + b_k] = b4.w;
    }
    __syncthreads();

    const int lane = tid & 31, wid = tid >> 5;
    const int wm = (wid & 3) * 32, wn = (wid >> 2) * 64;
    const int gr = lane >> 2, gc = lane & 3;

    float acc[2][8][4];
#pragma unroll
    for (int mi = 0; mi < 2; mi++)
#pragma unroll
        for (int ni = 0; ni < 8; ni++)
#pragma unroll
            for (int q = 0; q < 4; q++) acc[mi][ni][q] = 0.f;

    int buf = 0;
    for (int k0 = 8; k0 <= K; k0 += 8) {
        const bool has = (k0 < K);
        float4 a4, b4;
        if (has) {
            a4 = *(const float4*)(Ap + k0);
            b4 = *(const float4*)(Bp + (size_t)k0 * ldb);
        }
        unsigned ahi[2][4], alo[2][4];
#pragma unroll
        for (int mi = 0; mi < 2; mi++) {
            int m = wm + mi * 16 + gr;
            split_tf32(As[buf][m * 12 + gc],           ahi[mi][0], alo[mi][0]);
            split_tf32(As[buf][(m + 8) * 12 + gc],     ahi[mi][1], alo[mi][1]);
            split_tf32(As[buf][m * 12 + 4 + gc],       ahi[mi][2], alo[mi][2]);
            split_tf32(As[buf][(m + 8) * 12 + 4 + gc], ahi[mi][3], alo[mi][3]);
        }
#pragma unroll
        for (int ni = 0; ni < 8; ni++) {
            int n = wn + ni * 8 + gr;
            unsigned bh0, bl0, bh1, bl1;
            split_tf32(Bs[buf][n * 12 + gc],     bh0, bl0);
            split_tf32(Bs[buf][n * 12 + 4 + gc], bh1, bl1);
#pragma unroll
            for (int mi = 0; mi < 2; mi++) {
                MMA_TF32(acc[mi][ni], ahi[mi], bh0, bh1);
                MMA_TF32(acc[mi][ni], ahi[mi], bl0, bl1);
                MMA_TF32(acc[mi][ni], alo[mi], bh0, bh1);
            }
        }
        if (has) {
            const int nb = buf ^ 1;
            *(float4*)(As[nb] + a_row * 12 + a_k) = a4;
            Bs[nb][(b_n + 0) * 12 + b_k] = b4.x;
            Bs[nb][(b_n + 1) * 12 + b_k] = b4.y;
            Bs[nb][(b_n + 2) * 12 + b_k] = b4.z;
            Bs[nb][(b_n + 3) * 12 + b_k] = b4.w;
            __syncthreads();
            buf = nb;
        }
    }

#pragma unroll
    for (int mi = 0; mi < 2; mi++)
#pragma unroll
        for (int ni = 0; ni < 8; ni++) {
            int row = row0 + wm + mi * 16 + gr;
            int col = col0 + wn + ni * 8 + gc * 2;
            float bx = 0.f, by = 0.f;
            if (bias) { bx = bias[col]; by = bias[col + 1]; }
            float2 v0 = { acc[mi][ni][0] + bx, acc[mi][ni][1] + by };
            *(float2*)(C + (size_t)row * ldc + col) = v0;
            float2 v1 = { acc[mi][ni][2] + bx, acc[mi][ni][3] + by };
            *(float2*)(C + (size_t)(row + 8) * ldc + col) = v1;
        }
}

// ---------------------------------------------------------------------------
// topk v2: 2 query rows per 256-thread block (128 threads per row).
// Same exact selection math as R12 (bitonic warp threshold -> exact prefilter,
// scan compaction, rank-select on composite keys == jax.lax.top_k ties).
// PV vectorized: 8 key-groups x 16 float4-lanes + shfl/smem tree reduction.
// ---------------------------------------------------------------------------
__global__ void __launch_bounds__(256, 7) topk_attn(
    const float* __restrict__ S, const float* __restrict__ KV, float* __restrict__ O)
{
    __shared__ __align__(16) unsigned long long ckey[2][528];
    __shared__ float warpthr[2][4];
    __shared__ float selv[2][64];
    __shared__ int   seli[2][64];
    __shared__ float s_wsum[2];
    __shared__ int   s_ncand[2];
    __shared__ float w[2][64];
    __shared__ float part[2][4][64];

    const int tid  = threadIdx.x;
    const int sub  = tid >> 7;          // row within block (0/1)
    const int rtid = tid & 127;
    const int r  = blockIdx.x * 2 + sub;
    const int bh = r >> 11, i = r & 2047;
    const int b  = bh >> 3, h = bh & 7;
    const float* srow = S + (size_t)r * NK;

    const int lane = tid & 31, wrp = rtid >> 5;   // warp-in-row 0..3
    if (rtid == 0) s_ncand[sub] = 0;

    float vals[16];
#pragma unroll
    for (int t = 0; t < 4; t++) {
        float4 v = __ldcs((const float4*)srow + rtid + t * 128);
        vals[t * 4 + 0] = v.x; vals[t * 4 + 1] = v.y;
        vals[t * 4 + 2] = v.z; vals[t * 4 + 3] = v.w;
    }
    float tmax = vals[0];
#pragma unroll
    for (int t = 1; t < 16; t++) tmax = fmaxf(tmax, vals[t]);

    // warp bitonic sort (descending) of the 32 thread-maxes (warps never straddle rows)
    {
        float v = tmax;
#pragma unroll
        for (int k = 2; k <= 32; k <<= 1) {
#pragma unroll
            for (int j = k >> 1; j > 0; j >>= 1) {
                float o = __shfl_xor_sync(0xffffffffu, v, j);
                bool ascBlock = ((lane & k) != 0);
                bool upper    = ((lane & j) != 0);
                v = (upper == ascBlock) ? fmaxf(v, o) : fminf(v, o);
            }
        }
        float t_w = __shfl_sync(0xffffffffu, v, 15);   // 16th largest in warp
        if (lane == 0) warpthr[sub][wrp] = t_w;
    }
    __syncthreads();
    const float thr = fminf(fminf(warpthr[sub][0], warpthr[sub][1]),
                            fminf(warpthr[sub][2], warpthr[sub][3]));

    // scan-based compaction of candidates (v >= thr)
    {
        int cnt = 0;
#pragma unroll
        for (int t = 0; t < 16; t++) cnt += (vals[t] >= thr) ? 1 : 0;
        int pfx = cnt;
#pragma unroll
        for (int off = 1; off < 32; off <<= 1) {
            int o = __shfl_up_sync(0xffffffffu, pfx, off);
            if (lane >= off) pfx += o;
        }
        int wbase = 0;
        if (lane == 31) wbase = atomicAdd(&s_ncand[sub], pfx);
        wbase = __shfl_sync(0xffffffffu, wbase, 31);
        int p = wbase + pfx - cnt;
#pragma unroll
        for (int t = 0; t < 16; t++) {
            if (vals[t] >= thr) {
                if (p < CCAP) {
                    int j = (rtid + (t >> 2) * 128) * 4 + (t & 3);
                    ckey[sub][p] =
                        ((unsigned long long)fkey(vals[t]) << 32) | (unsigned)(2047 - j);
                }
                p++;
            }
        }
    }
    __syncthreads();
    const int nc = (s_ncand[sub] < CCAP) ? s_ncand[sub] : CCAP;
    if (rtid == 0) ckey[sub][nc] = 0ull;    // pad so paired reads are safe
    __syncthreads();

    // exact top-64 by rank over candidates (vectorized broadcast smem reads)
    for (int c = rtid; c < nc; c += 128) {
        unsigned long long k = ckey[sub][c];
        int rk = 0;
        for (int o = 0; o < nc; o += 2) {
            ulonglong2 kk = *(const ulonglong2*)&ckey[sub][o];
            rk += (kk.x > k) + (kk.y > k);
        }
        if (rk < KKEEP) {
            selv[sub][rk] = unfkey((unsigned)(k >> 32));
            seli[sub][rk] = 2047 - (int)(k & 0xffffffffu);
        }
    }
    __syncthreads();   // selv[sub][0] = row max

    if (rtid < 64) w[sub][rtid] = expf(selv[sub][rtid] - selv[sub][0]);
    __syncthreads();
    if (rtid < 32) {
        float s = w[sub][rtid] + w[sub][rtid + 32];
#pragma unroll
        for (int off = 16; off; off >>= 1)
            s += __shfl_xor_sync(0xffffffffu, s, off);
        if (rtid == 0) s_wsum[sub] = s;
    }
    __syncthreads();

    // PV: 8 key-groups x 16 float4-lanes per row; shfl + smem tree reduction
    {
        const int kg = rtid >> 4;            // 0..7 (8 keys each)
        const int ln = rtid & 15;            // float4 lane: dims ln*4..ln*4+3
        const float* Vb = KV + (size_t)b * NK * (2 * INNER) + INNER + h * HD + ln * 4;
        float4 a4 = make_float4(0.f, 0.f, 0.f, 0.f);
#pragma unroll
        for (int k = 0; k < 8; k++) {
            int idx = kg * 8 + k;
            float wk = w[sub][idx];
            float4 v4 = *(const float4*)(Vb + (size_t)seli[sub][idx] * (2 * INNER));
            a4.x += wk * v4.x; a4.y += wk * v4.y;
            a4.z += wk * v4.z; a4.w += wk * v4.w;
        }
        // combine kg pairs within warp (lanes 0-15 receive lanes 16-31)
        a4.x += __shfl_down_sync(0xffffffffu, a4.x, 16);
        a4.y += __shfl_down_sync(0xffffffffu, a4.y, 16);
        a4.z += __shfl_down_sync(0xffffffffu, a4.z, 16);
        a4.w += __shfl_down_sync(0xffffffffu, a4.w, 16);
        if (lane < 16)
            *(float4*)&part[sub][wrp][ln * 4] = a4;
    }
    __syncthreads();
    if (rtid < 64) {
        const int d = rtid;
        float o = (part[sub][0][d] + part[sub][1][d]) +
                  (part[sub][2][d] + part[sub][3][d]);
        o /= s_wsum[sub];
        O[((size_t)(b * NQ + i)) * INNER + h * HD + d] = o;
    }
}

// ---------------------------------------------------------------------------
extern "C" void kernel_launch(void* const* d_in, const int* in_sizes, int n_in,
                              void* d_out, int out_size)
{
    const float* x    = (const float*)d_in[0];
    const float* ctx  = (const float*)d_in[1];
    const float* Wq   = (const float*)d_in[2];
    const float* Wkv  = (const float*)d_in[3];
    const float* Wout = (const float*)d_in[4];
    const float* bout = (const float*)d_in[5];
    float* out = (float*)d_out;

    float *pQ, *pKV, *pS, *pO;
    cudaGetSymbolAddress((void**)&pQ,  g_Q);
    cudaGetSymbolAddress((void**)&pKV, g_KV);
    cudaGetSymbolAddress((void**)&pS,  g_S);
    cudaGetSymbolAddress((void**)&pO,  g_O);

    const int simSmem = 2 * 128 * 68 * sizeof(float);   // 69632 B
    cudaFuncSetAttribute(sim_tf32, cudaFuncAttributeMaxDynamicSharedMemorySize, simSmem);

    dim3 blk(256);
    // Q = x @ Wq   (fp32; feeds selection)
    sgemm_nn<<<dim3(INNER / 128, BATCH * NQ / 128), blk>>>(
        x, Wq, pQ, BATCH * NQ, INNER, DQ, DQ, INNER, INNER);
    // K-half: ctx @ Wkv[:, 0:512]  (fp32; feeds selection)
    sgemm_nn<<<dim3(INNER / 128, BATCH * NK / 128), blk>>>(
        ctx, Wkv, pKV, BATCH * NK, INNER, DQ, DQ, 2 * INNER, 2 * INNER);
    // V-half: ctx @ Wkv[:, 512:1024]  (3xTF32; post-selection, safe)
    gemm_tf32_nn<<<dim3(INNER / 128, BATCH * NK / 128), blk>>>(
        ctx, Wkv + INNER, nullptr, pKV + INNER,
        BATCH * NK, INNER, DQ, DQ, 2 * INNER, 2 * INNER);
    // sim = Q @ K^T * scale (3-term TF32; 512 threads, 2 blocks/SM)
    sim_tf32<<<dim3(NK / 128, NQ / 128, BATCH * NH), dim3(512), simSmem>>>(pQ, pKV, pS);
    // exact top-64 + softmax + sparse PV (2 rows per block)
    topk_attn<<<dim3(BATCH * NH * NQ / 2), dim3(256)>>>(pS, pKV, pO);
    // out = O @ Wout + bout (3xTF32)
    gemm_tf32_nn<<<dim3(DQ / 128, BATCH * NQ / 128), blk>>>(
        pO, Wout, bout, out, BATCH * NQ, DQ, INNER, INNER, DQ, DQ);
}

// round 15
// speedup vs baseline: 3.3689x; 1.0385x over previous
#include <cuda_runtime.h>

#define BATCH 4
#define NQ    2048
#define NK    2048
#define DQ    1024
#define NH    8
#define HD    64
#define INNER 512
#define KKEEP 64
#define CCAP  512

// Scratch (device globals; allocation-free contract)
__device__ float g_Q [BATCH * NQ * INNER];          // 16.8 MB
__device__ float g_KV[BATCH * NK * 2 * INNER];      // 33.5 MB  (K: cols 0..511, V: 512..1023)
__device__ float g_S [134217728];                   // 512 MB   sim [B*H][NQ][NK]
__device__ float g_O [BATCH * NQ * INNER];          // 16.8 MB

// ---- tf32 split helpers + warp MMA --------------------------------------------
__device__ __forceinline__ void split_tf32(float v, unsigned& hi, unsigned& lo) {
    asm("cvt.rna.tf32.f32 %0, %1;" : "=r"(hi) : "f"(v));
    float l = v - __uint_as_float(hi);
    asm("cvt.rna.tf32.f32 %0, %1;" : "=r"(lo) : "f"(l));
}

#define MMA_TF32(c, a, b0, b1) \
    asm("mma.sync.aligned.m16n8k8.row.col.f32.tf32.tf32.f32 " \
        "{%0,%1,%2,%3}, {%4,%5,%6,%7}, {%8,%9}, {%0,%1,%2,%3};" \
        : "+f"((c)[0]), "+f"((c)[1]), "+f"((c)[2]), "+f"((c)[3]) \
        : "r"((a)[0]), "r"((a)[1]), "r"((a)[2]), "r"((a)[3]), "r"(b0), "r"(b1))

__device__ __forceinline__ unsigned fkey(float f) {
    unsigned u = __float_as_uint(f);
    return (u & 0x80000000u) ? ~u : (u | 0x80000000u);
}
__device__ __forceinline__ float unfkey(unsigned k) {
    unsigned u = (k & 0x80000000u) ? (k & 0x7fffffffu) : ~k;
    return __uint_as_float(u);
}

// ---------------------------------------------------------------------------
// fp32 SGEMM body (NN), double-buffered (bitwise-identical to R13 sgemm_nn).
// Smem provided by caller (2*8*128 floats As + same Bs = 16384 B).
// ---------------------------------------------------------------------------
__device__ __forceinline__ void sgemm_body(
    float* smem, int bxx, int byy,
    const float* __restrict__ A, const float* __restrict__ Bm,
    float* __restrict__ C, int K, int lda, int ldb, int ldc)
{
    float (*As)[8][128] = (float (*)[8][128])smem;
    float (*Bs)[8][128] = (float (*)[8][128])(smem + 2048);
    const int tid  = threadIdx.x;
    const int row0 = byy * 128, col0 = bxx * 128;
    const int tx   = tid & 15, ty = tid >> 4;
    const int a_row = tid >> 1, a_k = (tid & 1) * 4;
    const int b_k   = tid >> 5, b_col = (tid & 31) * 4;
    const float* Ap = A  + (size_t)(row0 + a_row) * lda + a_k;
    const float* Bp = Bm + (size_t)b_k * ldb + col0 + b_col;

    float acc[8][8];
#pragma unroll
    for (int i = 0; i < 8; i++)
#pragma unroll
        for (int j = 0; j < 8; j++) acc[i][j] = 0.f;

    {
        float4 av = *(const float4*)Ap;
        float4 bv = *(const float4*)Bp;
        As[0][a_k + 0][a_row] = av.x;
        As[0][a_k + 1][a_row] = av.y;
        As[0][a_k + 2][a_row] = av.z;
        As[0][a_k + 3][a_row] = av.w;
        *(float4*)&Bs[0][b_k][b_col] = bv;
    }
    __syncthreads();

    int buf = 0;
    for (int k0 = 8; k0 <= K; k0 += 8) {
        const bool has = (k0 < K);
        float4 av, bv;
        if (has) {
            av = *(const float4*)(Ap + k0);
            bv = *(const float4*)(Bp + (size_t)k0 * ldb);
        }
#pragma unroll
        for (int kk = 0; kk < 8; kk++) {
            float af[8], bf[8];
            *(float4*)&af[0] = *(const float4*)&As[buf][kk][ty * 4];
            *(float4*)&af[4] = *(const float4*)&As[buf][kk][ty * 4 + 64];
            *(float4*)&bf[0] = *(const float4*)&Bs[buf][kk][tx * 4];
            *(float4*)&bf[4] = *(const float4*)&Bs[buf][kk][tx * 4 + 64];
#pragma unroll
            for (int i = 0; i < 8; i++)
#pragma unroll
                for (int j = 0; j < 8; j++)
                    acc[i][j] += af[i] * bf[j];
        }
        if (has) {
            const int nb = buf ^ 1;
            As[nb][a_k + 0][a_row] = av.x;
            As[nb][a_k + 1][a_row] = av.y;
            As[nb][a_k + 2][a_row] = av.z;
            As[nb][a_k + 3][a_row] = av.w;
            *(float4*)&Bs[nb][b_k][b_col] = bv;
            __syncthreads();
            buf = nb;
        }
    }

#pragma unroll
    for (int ih = 0; ih < 2; ih++)
#pragma unroll
        for (int ii = 0; ii < 4; ii++) {
            int row = row0 + ty * 4 + ih * 64 + ii;
            float* Cp = C + (size_t)row * ldc + col0;
#pragma unroll
            for (int jh = 0; jh < 2; jh++) {
                int c = tx * 4 + jh * 64;
                float4 v;
                v.x = acc[ih * 4 + ii][jh * 4 + 0];
                v.y = acc[ih * 4 + ii][jh * 4 + 1];
                v.z = acc[ih * 4 + ii][jh * 4 + 2];
                v.w = acc[ih * 4 + ii][jh * 4 + 3];
                *(float4*)(Cp + c) = v;
            }
        }
}

// ---------------------------------------------------------------------------
// 3xTF32 MMA GEMM body (NN), bitwise-identical to R13 gemm_tf32_nn.
// Smem provided by caller (2*1536 floats As + same Bs = 24576 B).
// ---------------------------------------------------------------------------
__device__ __forceinline__ void tf32gemm_body(
    float* smem, int bxx, int byy,
    const float* __restrict__ A, const float* __restrict__ Bm,
    const float* __restrict__ bias, float* __restrict__ C,
    int K, int lda, int ldb, int ldc)
{
    float (*As)[128 * 12] = (float (*)[128 * 12])smem;
    float (*Bs)[128 * 12] = (float (*)[128 * 12])(smem + 2 * 128 * 12);
    const int tid  = threadIdx.x;
    const int row0 = byy * 128, col0 = bxx * 128;
    const int a_row = tid >> 1, a_k = (tid & 1) * 4;
    const int b_k   = tid >> 5, b_n = (tid & 31) * 4;
    const float* Ap = A  + (size_t)(row0 + a_row) * lda + a_k;
    const float* Bp = Bm + (size_t)b_k * ldb + col0 + b_n;

    {
        float4 a4 = *(const float4*)Ap;
        *(float4*)(As[0] + a_row * 12 + a_k) = a4;
        float4 b4 = *(const float4*)Bp;
        Bs[0][(b_n + 0) * 12 + b_k] = b4.x;
        Bs[0][(b_n + 1) * 12 + b_k] = b4.y;
        Bs[0][(b_n + 2) * 12 + b_k] = b4.z;
        Bs[0][(b_n + 3) * 12 + b_k] = b4.w;
    }
    __syncthreads();

    const int lane = tid & 31, wid = tid >> 5;
    const int wm = (wid & 3) * 32, wn = (wid >> 2) * 64;
    const int gr = lane >> 2, gc = lane & 3;

    float acc[2][8][4];
#pragma unroll
    for (int mi = 0; mi < 2; mi++)
#pragma unroll
        for (int ni = 0; ni < 8; ni++)
#pragma unroll
            for (int q = 0; q < 4; q++) acc[mi][ni][q] = 0.f;

    int buf = 0;
    for (int k0 = 8; k0 <= K; k0 += 8) {
        const bool has = (k0 < K);
        float4 a4, b4;
        if (has) {
            a4 = *(const float4*)(Ap + k0);
            b4 = *(const float4*)(Bp + (size_t)k0 * ldb);
        }
        unsigned ahi[2][4], alo[2][4];
#pragma unroll
        for (int mi = 0; mi < 2; mi++) {
            int m = wm + mi * 16 + gr;
            split_tf32(As[buf][m * 12 + gc],           ahi[mi][0], alo[mi][0]);
            split_tf32(As[buf][(m + 8) * 12 + gc],     ahi[mi][1], alo[mi][1]);
            split_tf32(As[buf][m * 12 + 4 + gc],       ahi[mi][2], alo[mi][2]);
            split_tf32(As[buf][(m + 8) * 12 + 4 + gc], ahi[mi][3], alo[mi][3]);
        }
#pragma unroll
        for (int ni = 0; ni < 8; ni++) {
            int n = wn + ni * 8 + gr;
            unsigned bh0, bl0, bh1, bl1;
            split_tf32(Bs[buf][n * 12 + gc],     bh0, bl0);
            split_tf32(Bs[buf][n * 12 + 4 + gc], bh1, bl1);
#pragma unroll
            for (int mi = 0; mi < 2; mi++) {
                MMA_TF32(acc[mi][ni], ahi[mi], bh0, bh1);
                MMA_TF32(acc[mi][ni], ahi[mi], bl0, bl1);
                MMA_TF32(acc[mi][ni], alo[mi], bh0, bh1);
            }
        }
        if (has) {
            const int nb = buf ^ 1;
            *(float4*)(As[nb] + a_row * 12 + a_k) = a4;
            Bs[nb][(b_n + 0) * 12 + b_k] = b4.x;
            Bs[nb][(b_n + 1) * 12 + b_k] = b4.y;
            Bs[nb][(b_n + 2) * 12 + b_k] = b4.z;
            Bs[nb][(b_n + 3) * 12 + b_k] = b4.w;
            __syncthreads();
            buf = nb;
        }
    }

#pragma unroll
    for (int mi = 0; mi < 2; mi++)
#pragma unroll
        for (int ni = 0; ni < 8; ni++) {
            int row = row0 + wm + mi * 16 + gr;
            int col = col0 + wn + ni * 8 + gc * 2;
            float bx = 0.f, by = 0.f;
            if (bias) { bx = bias[col]; by = bias[col + 1]; }
            float2 v0 = { acc[mi][ni][0] + bx, acc[mi][ni][1] + by };
            *(float2*)(C + (size_t)row * ldc + col) = v0;
            float2 v1 = { acc[mi][ni][2] + bx, acc[mi][ni][3] + by };
            *(float2*)(C + (size_t)(row + 8) * ldc + col) = v1;
        }
}

// ---------------------------------------------------------------------------
// FUSED projections: blocks 0-255 Q-proj (fp32), 256-511 K-proj (fp32),
// 512-767 V-proj (3xTF32).  Pipe overlap: FFMA blocks and tensor blocks
// co-resident per SM.  Arithmetic bitwise-identical to the separate kernels.
// ---------------------------------------------------------------------------
__global__ void __launch_bounds__(256) proj_fused(
    const float* __restrict__ x, const float* __restrict__ ctx,
    const float* __restrict__ Wq, const float* __restrict__ Wkv,
    float* __restrict__ Q, float* __restrict__ KV)
{
    extern __shared__ float dsm[];
    const int bid = blockIdx.x;
    if (bid < 256) {
        // Q = x @ Wq   [8192,1024]@[1024,512]
        sgemm_body(dsm, bid & 3, bid >> 2, x, Wq, Q, DQ, DQ, INNER, INNER);
    } else if (bid < 512) {
        // K-half: ctx @ Wkv[:,0:512]
        int t = bid - 256;
        sgemm_body(dsm, t & 3, t >> 2, ctx, Wkv, KV, DQ, DQ, 2 * INNER, 2 * INNER);
    } else {
        // V-half: ctx @ Wkv[:,512:1024]  (tensor pipe)
        int t = bid - 512;
        tf32gemm_body(dsm, t & 3, t >> 2, ctx, Wkv + INNER, nullptr, KV + INNER,
                      DQ, DQ, 2 * INNER, 2 * INNER);
    }
}

// ---------------------------------------------------------------------------
// sim via 3-term TF32 MMA (NT): S = 0.125 * Q_h . K_h^T   (unchanged R12 best)
// ---------------------------------------------------------------------------
__global__ void __launch_bounds__(512, 2) sim_tf32(
    const float* __restrict__ Q, const float* __restrict__ KV, float* __restrict__ S)
{
    extern __shared__ float sm[];
    float* Qs = sm;              // [128][68]
    float* Ks = sm + 128 * 68;   // [128][68]
    const int bh = blockIdx.z, b = bh >> 3, h = bh & 7;
    const int i0 = blockIdx.y * 128, j0 = blockIdx.x * 128;
    const int tid = threadIdx.x;

#pragma unroll
    for (int l = 0; l < 4; l++) {
        int idx = tid + l * 512;                 // 0..2047
        int row = idx >> 4, k0 = (idx & 15) * 4;
        float4 q4 = *(const float4*)(Q  + (size_t)(b * NQ + i0 + row) * INNER       + h * HD + k0);
        *(float4*)(Qs + row * 68 + k0) = q4;
        float4 k4 = *(const float4*)(KV + (size_t)(b * NK + j0 + row) * (2 * INNER) + h * HD + k0);
        *(float4*)(Ks + row * 68 + k0) = k4;
    }
    __syncthreads();

    const int lane = tid & 31, wid = tid >> 5;   // wid 0..15
    const int wm = (wid & 3) * 32, wn = (wid >> 2) * 32;
    const int gr = lane >> 2, gc = lane & 3;

    float acc[2][4][4];
#pragma unroll
    for (int mi = 0; mi < 2; mi++)
#pragma unroll
        for (int ni = 0; ni < 4; ni++)
#pragma unroll
            for (int q = 0; q < 4; q++) acc[mi][ni][q] = 0.f;

#pragma unroll
    for (int k0 = 0; k0 < 64; k0 += 8) {
        unsigned ahi[2][4], alo[2][4];
#pragma unroll
        for (int mi = 0; mi < 2; mi++) {
            int m = wm + mi * 16 + gr;
            split_tf32(Qs[m * 68 + k0 + gc],           ahi[mi][0], alo[mi][0]);
            split_tf32(Qs[(m + 8) * 68 + k0 + gc],     ahi[mi][1], alo[mi][1]);
            split_tf32(Qs[m * 68 + k0 + 4 + gc],       ahi[mi][2], alo[mi][2]);
            split_tf32(Qs[(m + 8) * 68 + k0 + 4 + gc], ahi[mi][3], alo[mi][3]);
        }
#pragma unroll
        for (int ni = 0; ni < 4; ni++) {
            int n = wn + ni * 8 + gr;
            unsigned bh0, bl0, bh1, bl1;
            split_tf32(Ks[n * 68 + k0 + gc],     bh0, bl0);
            split_tf32(Ks[n * 68 + k0 + 4 + gc], bh1, bl1);
#pragma unroll
            for (int mi = 0; mi < 2; mi++) {
                MMA_TF32(acc[mi][ni], ahi[mi], bh0, bh1);
                MMA_TF32(acc[mi][ni], ahi[mi], bl0, bl1);
                MMA_TF32(acc[mi][ni], alo[mi], bh0, bh1);
            }
        }
    }

    const float scale = 0.125f;
#pragma unroll
    for (int mi = 0; mi < 2; mi++)
#pragma unroll
        for (int ni = 0; ni < 4; ni++) {
            int row = i0 + wm + mi * 16 + gr;
            int col = j0 + wn + ni * 8 + gc * 2;
            float2 v0 = { acc[mi][ni][0] * scale, acc[mi][ni][1] * scale };
            __stcs((float2*)(S + ((size_t)bh * NQ + row) * NK + col), v0);
            float2 v1 = { acc[mi][ni][2] * scale, acc[mi][ni][3] * scale };
            __stcs((float2*)(S + ((size_t)bh * NQ + row + 8) * NK + col), v1);
        }
}

// ---------------------------------------------------------------------------
// out-projection kernel (3xTF32), standalone wrapper around the body.
// ---------------------------------------------------------------------------
__global__ void __launch_bounds__(256) out_tf32(
    const float* __restrict__ A, const float* __restrict__ Bm,
    const float* __restrict__ bias, float* __restrict__ C)
{
    extern __shared__ float dsm[];
    tf32gemm_body(dsm, blockIdx.x, blockIdx.y, A, Bm, bias, C,
                  INNER, INNER, DQ, DQ);
}

// ---------------------------------------------------------------------------
// topk v2 (unchanged from R13): 2 rows per 256-thread block; exact top-64
// (bitonic warp threshold prefilter, scan compaction, rank-select composite
// keys == jax.lax.top_k ties), softmax, vectorized sparse PV.
// ---------------------------------------------------------------------------
__global__ void __launch_bounds__(256, 7) topk_attn(
    const float* __restrict__ S, const float* __restrict__ KV, float* __restrict__ O)
{
    __shared__ __align__(16) unsigned long long ckey[2][528];
    __shared__ float warpthr[2][4];
    __shared__ float selv[2][64];
    __shared__ int   seli[2][64];
    __shared__ float s_wsum[2];
    __shared__ int   s_ncand[2];
    __shared__ float w[2][64];
    __shared__ float part[2][4][64];

    const int tid  = threadIdx.x;
    const int sub  = tid >> 7;          // row within block (0/1)
    const int rtid = tid & 127;
    const int r  = blockIdx.x * 2 + sub;
    const int bh = r >> 11, i = r & 2047;
    const int b  = bh >> 3, h = bh & 7;
    const float* srow = S + (size_t)r * NK;

    const int lane = tid & 31, wrp = rtid >> 5;   // warp-in-row 0..3
    if (rtid == 0) s_ncand[sub] = 0;

    float vals[16];
#pragma unroll
    for (int t = 0; t < 4; t++) {
        float4 v = __ldcs((const float4*)srow + rtid + t * 128);
        vals[t * 4 + 0] = v.x; vals[t * 4 + 1] = v.y;
        vals[t * 4 + 2] = v.z; vals[t * 4 + 3] = v.w;
    }
    float tmax = vals[0];
#pragma unroll
    for (int t = 1; t < 16; t++) tmax = fmaxf(tmax, vals[t]);

    {
        float v = tmax;
#pragma unroll
        for (int k = 2; k <= 32; k <<= 1) {
#pragma unroll
            for (int j = k >> 1; j > 0; j >>= 1) {
                float o = __shfl_xor_sync(0xffffffffu, v, j);
                bool ascBlock = ((lane & k) != 0);
                bool upper    = ((lane & j) != 0);
                v = (upper == ascBlock) ? fmaxf(v, o) : fminf(v, o);
            }
        }
        float t_w = __shfl_sync(0xffffffffu, v, 15);   // 16th largest in warp
        if (lane == 0) warpthr[sub][wrp] = t_w;
    }
    __syncthreads();
    const float thr = fminf(fminf(warpthr[sub][0], warpthr[sub][1]),
                            fminf(warpthr[sub][2], warpthr[sub][3]));

    {
        int cnt = 0;
#pragma unroll
        for (int t = 0; t < 16; t++) cnt += (vals[t] >= thr) ? 1 : 0;
        int pfx = cnt;
#pragma unroll
        for (int off = 1; off < 32; off <<= 1) {
            int o = __shfl_up_sync(0xffffffffu, pfx, off);
            if (lane >= off) pfx += o;
        }
        int wbase = 0;
        if (lane == 31) wbase = atomicAdd(&s_ncand[sub], pfx);
        wbase = __shfl_sync(0xffffffffu, wbase, 31);
        int p = wbase + pfx - cnt;
#pragma unroll
        for (int t = 0; t < 16; t++) {
            if (vals[t] >= thr) {
                if (p < CCAP) {
                    int j = (rtid + (t >> 2) * 128) * 4 + (t & 3);
                    ckey[sub][p] =
                        ((unsigned long long)fkey(vals[t]) << 32) | (unsigned)(2047 - j);
                }
                p++;
            }
        }
    }
    __syncthreads();
    const int nc = (s_ncand[sub] < CCAP) ? s_ncand[sub] : CCAP;
    if (rtid == 0) ckey[sub][nc] = 0ull;
    __syncthreads();

    for (int c = rtid; c < nc; c += 128) {
        unsigned long long k = ckey[sub][c];
        int rk = 0;
        for (int o = 0; o < nc; o += 2) {
            ulonglong2 kk = *(const ulonglong2*)&ckey[sub][o];
            rk += (kk.x > k) + (kk.y > k);
        }
        if (rk < KKEEP) {
            selv[sub][rk] = unfkey((unsigned)(k >> 32));
            seli[sub][rk] = 2047 - (int)(k & 0xffffffffu);
        }
    }
    __syncthreads();   // selv[sub][0] = row max

    if (rtid < 64) w[sub][rtid] = expf(selv[sub][rtid] - selv[sub][0]);
    __syncthreads();
    if (rtid < 32) {
        float s = w[sub][rtid] + w[sub][rtid + 32];
#pragma unroll
        for (int off = 16; off; off >>= 1)
            s += __shfl_xor_sync(0xffffffffu, s, off);
        if (rtid == 0) s_wsum[sub] = s;
    }
    __syncthreads();

    {
        const int kg = rtid >> 4;            // 0..7 (8 keys each)
        const int ln = rtid & 15;            // float4 lane
        const float* Vb = KV + (size_t)b * NK * (2 * INNER) + INNER + h * HD + ln * 4;
        float4 a4 = make_float4(0.f, 0.f, 0.f, 0.f);
#pragma unroll
        for (int k = 0; k < 8; k++) {
            int idx = kg * 8 + k;
            float wk = w[sub][idx];
            float4 v4 = *(const float4*)(Vb + (size_t)seli[sub][idx] * (2 * INNER));
            a4.x += wk * v4.x; a4.y += wk * v4.y;
            a4.z += wk * v4.z; a4.w += wk * v4.w;
        }
        a4.x += __shfl_down_sync(0xffffffffu, a4.x, 16);
        a4.y += __shfl_down_sync(0xffffffffu, a4.y, 16);
        a4.z += __shfl_down_sync(0xffffffffu, a4.z, 16);
        a4.w += __shfl_down_sync(0xffffffffu, a4.w, 16);
        if (lane < 16)
            *(float4*)&part[sub][wrp][ln * 4] = a4;
    }
    __syncthreads();
    if (rtid < 64) {
        const int d = rtid;
        float o = (part[sub][0][d] + part[sub][1][d]) +
                  (part[sub][2][d] + part[sub][3][d]);
        o /= s_wsum[sub];
        O[((size_t)(b * NQ + i)) * INNER + h * HD + d] = o;
    }
}

// ---------------------------------------------------------------------------
extern "C" void kernel_launch(void* const* d_in, const int* in_sizes, int n_in,
                              void* d_out, int out_size)
{
    const float* x    = (const float*)d_in[0];
    const float* ctx  = (const float*)d_in[1];
    const float* Wq   = (const float*)d_in[2];
    const float* Wkv  = (const float*)d_in[3];
    const float* Wout = (const float*)d_in[4];
    const float* bout = (const float*)d_in[5];
    float* out = (float*)d_out;

    float *pQ, *pKV, *pS, *pO;
    cudaGetSymbolAddress((void**)&pQ,  g_Q);
    cudaGetSymbolAddress((void**)&pKV, g_KV);
    cudaGetSymbolAddress((void**)&pS,  g_S);
    cudaGetSymbolAddress((void**)&pO,  g_O);

    const int simSmem  = 2 * 128 * 68 * sizeof(float);   // 69632 B
    const int projSmem = 2 * 2 * 128 * 12 * sizeof(float); // 24576 B (max of paths)
    cudaFuncSetAttribute(sim_tf32, cudaFuncAttributeMaxDynamicSharedMemorySize, simSmem);

    // FUSED Q/K/V projections (pipe-overlapped; bitwise-identical math)
    proj_fused<<<dim3(768), dim3(256), projSmem>>>(x, ctx, Wq, Wkv, pQ, pKV);
    // sim = Q @ K^T * scale (3-term TF32; 512 threads, 2 blocks/SM)
    sim_tf32<<<dim3(NK / 128, NQ / 128, BATCH * NH), dim3(512), simSmem>>>(pQ, pKV, pS);
    // exact top-64 + softmax + sparse PV (2 rows per block)
    topk_attn<<<dim3(BATCH * NH * NQ / 2), dim3(256)>>>(pS, pKV, pO);
    // out = O @ Wout + bout (3xTF32)
    out_tf32<<<dim3(DQ / 128, BATCH * NQ / 128), dim3(256), projSmem>>>(
        pO, Wout, bout, out);
}